// round 1
// baseline (speedup 1.0000x reference)
#include <cuda_runtime.h>
#include <cuda_bf16.h>
#include <math.h>

// Problem constants
#define BB 2
#define SS 1024
#define DD 768
#define HH 12
#define DKK 64
#define DFFF 3072
#define VV 32000
#define LL 4
#define MM (BB*SS)   // 2048

// ---------------- scratch (static device globals; no allocation) -------------
__device__ float g_h  [MM*DD];
__device__ float g_q  [MM*DD];
__device__ float g_k  [MM*DD];
__device__ float g_v  [MM*DD];
__device__ float g_av [MM*DD];
__device__ float g_tmp[MM*DD];
__device__ float g_ff [MM*DFFF];

// ---------------- embedding + sinusoidal PE ---------------------------------
__global__ void embed_kernel(const int* __restrict__ x, const float* __restrict__ emb,
                             float* __restrict__ h) {
    int row = blockIdx.x;                 // b*S + s
    int s = row & (SS - 1);
    int tok = x[row];
    for (int c = threadIdx.x; c < DD; c += blockDim.x) {
        // match jnp f32 math: scale = 10000^(2*(c/2)/D); ang = s/scale
        float ef = (float)(c & ~1) / (float)DD;
        float sc = powf(10000.0f, ef);
        float ang = (float)s / sc;
        float pe = (c & 1) ? cosf(ang) : sinf(ang);
        h[(size_t)row * DD + c] = emb[(size_t)tok * DD + c] + pe;
    }
}

// ---------------- 128x128x16 fp32 tiled GEMM, fused epilogues ----------------
// C[M,N] = A[M,K] @ B[K,N]   epi: 0=none, 1=+bias, 2=gelu(+bias)
__device__ __forceinline__ float gelu_exact(float x) {
    return 0.5f * x * (1.0f + erff(x * 0.7071067811865476f));
}

__global__ __launch_bounds__(256, 2)
void gemm128(const float* __restrict__ A, const float* __restrict__ B,
             const float* __restrict__ bias, float* __restrict__ C,
             int N, int K, int epi) {
    __shared__ float As[16][128];
    __shared__ float Bs[16][128];
    int bx = blockIdx.x, by = blockIdx.y;
    int tid = threadIdx.x;
    int tx = tid & 15, ty = tid >> 4;

    const float* Ab = A + (size_t)by * 128 * K;
    const float* Bb = B + (size_t)bx * 128;

    float acc[8][8];
    #pragma unroll
    for (int i = 0; i < 8; i++)
        #pragma unroll
        for (int j = 0; j < 8; j++) acc[i][j] = 0.f;

    int arow = tid >> 2;           // 0..63
    int ac4  = (tid & 3) << 2;     // 0,4,8,12
    int brow = tid >> 5;           // 0..7
    int bc4  = (tid & 31) << 2;    // 0..124

    for (int kt = 0; kt < K; kt += 16) {
        #pragma unroll
        for (int r = 0; r < 2; r++) {
            int row = arow + r * 64;
            float4 av = *reinterpret_cast<const float4*>(Ab + (size_t)row * K + kt + ac4);
            As[ac4 + 0][row] = av.x; As[ac4 + 1][row] = av.y;
            As[ac4 + 2][row] = av.z; As[ac4 + 3][row] = av.w;
        }
        #pragma unroll
        for (int r = 0; r < 2; r++) {
            int row = brow + r * 8;
            float4 bv = *reinterpret_cast<const float4*>(Bb + (size_t)(kt + row) * N + bc4);
            *reinterpret_cast<float4*>(&Bs[row][bc4]) = bv;
        }
        __syncthreads();
        #pragma unroll
        for (int k = 0; k < 16; k++) {
            float af[8], bf[8];
            *reinterpret_cast<float4*>(&af[0]) = *reinterpret_cast<const float4*>(&As[k][ty * 4]);
            *reinterpret_cast<float4*>(&af[4]) = *reinterpret_cast<const float4*>(&As[k][64 + ty * 4]);
            *reinterpret_cast<float4*>(&bf[0]) = *reinterpret_cast<const float4*>(&Bs[k][tx * 4]);
            *reinterpret_cast<float4*>(&bf[4]) = *reinterpret_cast<const float4*>(&Bs[k][64 + tx * 4]);
            #pragma unroll
            for (int i = 0; i < 8; i++)
                #pragma unroll
                for (int j = 0; j < 8; j++) acc[i][j] += af[i] * bf[j];
        }
        __syncthreads();
    }

    #pragma unroll
    for (int i = 0; i < 8; i++) {
        int row = by * 128 + ((i < 4) ? (ty * 4 + i) : (64 + ty * 4 + (i - 4)));
        #pragma unroll
        for (int jj = 0; jj < 2; jj++) {
            int col = bx * 128 + ((jj == 0) ? (tx * 4) : (64 + tx * 4));
            float r0 = acc[i][jj * 4 + 0], r1 = acc[i][jj * 4 + 1];
            float r2 = acc[i][jj * 4 + 2], r3 = acc[i][jj * 4 + 3];
            if (epi >= 1) {
                r0 += bias[col + 0]; r1 += bias[col + 1];
                r2 += bias[col + 2]; r3 += bias[col + 3];
            }
            if (epi == 2) {
                r0 = gelu_exact(r0); r1 = gelu_exact(r1);
                r2 = gelu_exact(r2); r3 = gelu_exact(r3);
            }
            float4 w; w.x = r0; w.y = r1; w.z = r2; w.w = r3;
            *reinterpret_cast<float4*>(C + (size_t)row * N + col) = w;
        }
    }
}

// ---------------- streaming causal attention (no-max custom softmax) --------
// out[q,d] = sum_{k<q} exp(s_k/8) v_k[d] / (sum exp + 1e-9)
#define ATTN_SMEM ((3 * 64 * 65 + 64) * 4)

__global__ void attn_kernel(const float* __restrict__ q, const float* __restrict__ k,
                            const float* __restrict__ v, float* __restrict__ o) {
    extern __shared__ float sm[];
    float* qs    = sm;                 // [64][65]
    float* es    = sm + 64 * 65;       // K tile, reused as e tile
    float* vs    = sm + 2 * 64 * 65;   // [64][65]
    float* denom = sm + 3 * 64 * 65;   // [64]

    int qt = blockIdx.x;
    int bh = blockIdx.y;
    int b = bh / HH, hh = bh % HH;
    const float* qb = q + (size_t)b * SS * DD + hh * DKK;
    const float* kb = k + (size_t)b * SS * DD + hh * DKK;
    const float* vb = v + (size_t)b * SS * DD + hh * DKK;

    int tid = threadIdx.x;
    int tx = tid & 15, ty = tid >> 4;

    for (int idx = tid; idx < 64 * 64; idx += 256) {
        int r = idx >> 6, c = idx & 63;
        qs[r * 65 + c] = qb[(size_t)(qt * 64 + r) * DD + c];
    }
    if (tid < 64) denom[tid] = 0.f;
    float oacc[4][4];
    #pragma unroll
    for (int i = 0; i < 4; i++)
        #pragma unroll
        for (int j = 0; j < 4; j++) oacc[i][j] = 0.f;
    __syncthreads();

    for (int kt = 0; kt <= qt; kt++) {
        for (int idx = tid; idx < 64 * 64; idx += 256) {
            int r = idx >> 6, c = idx & 63;
            es[r * 65 + c] = kb[(size_t)(kt * 64 + r) * DD + c];
            vs[r * 65 + c] = vb[(size_t)(kt * 64 + r) * DD + c];
        }
        __syncthreads();

        float s[4][4];
        #pragma unroll
        for (int i = 0; i < 4; i++)
            #pragma unroll
            for (int j = 0; j < 4; j++) s[i][j] = 0.f;
        #pragma unroll 8
        for (int d = 0; d < 64; d++) {
            float aq[4], ak[4];
            #pragma unroll
            for (int i = 0; i < 4; i++) aq[i] = qs[(ty * 4 + i) * 65 + d];
            #pragma unroll
            for (int j = 0; j < 4; j++) ak[j] = es[(tx * 4 + j) * 65 + d];
            #pragma unroll
            for (int i = 0; i < 4; i++)
                #pragma unroll
                for (int j = 0; j < 4; j++) s[i][j] += aq[i] * ak[j];
        }
        __syncthreads();  // done reading K tile; safe to overwrite with e

        #pragma unroll
        for (int i = 0; i < 4; i++) {
            int qg = qt * 64 + ty * 4 + i;
            float rs = 0.f;
            #pragma unroll
            for (int j = 0; j < 4; j++) {
                int kg = kt * 64 + tx * 4 + j;
                float e = (kg < qg) ? expf(s[i][j] * 0.125f) : 0.f;
                es[(ty * 4 + i) * 65 + (tx * 4 + j)] = e;
                rs += e;
            }
            atomicAdd(&denom[ty * 4 + i], rs);
        }
        __syncthreads();

        #pragma unroll 4
        for (int kk = 0; kk < 64; kk++) {
            float ef[4], vf[4];
            #pragma unroll
            for (int i = 0; i < 4; i++) ef[i] = es[(ty * 4 + i) * 65 + kk];
            #pragma unroll
            for (int j = 0; j < 4; j++) vf[j] = vs[kk * 65 + tx * 4 + j];
            #pragma unroll
            for (int i = 0; i < 4; i++)
                #pragma unroll
                for (int j = 0; j < 4; j++) oacc[i][j] += ef[i] * vf[j];
        }
        __syncthreads();
    }

    #pragma unroll
    for (int i = 0; i < 4; i++) {
        int qg = qt * 64 + ty * 4 + i;
        float dn = denom[ty * 4 + i] + 1e-9f;
        #pragma unroll
        for (int j = 0; j < 4; j++)
            o[(size_t)(b * SS + qg) * DD + hh * DKK + tx * 4 + j] = oacc[i][j] / dn;
    }
}

// ---------------- fused residual-add + LayerNorm (in-place on h) ------------
__device__ __forceinline__ float block_reduce_sum(float v, float* sh) {
    int tid = threadIdx.x;
    #pragma unroll
    for (int o = 16; o; o >>= 1) v += __shfl_xor_sync(0xffffffffu, v, o);
    if ((tid & 31) == 0) sh[tid >> 5] = v;
    __syncthreads();
    float r = 0.f;
    if (tid < 8) r = sh[tid];
    if (tid < 32) {
        #pragma unroll
        for (int o = 4; o; o >>= 1) r += __shfl_xor_sync(0xffffffffu, r, o);
    }
    if (tid == 0) sh[0] = r;
    __syncthreads();
    float out = sh[0];
    __syncthreads();
    return out;
}

__global__ void ln_kernel(float* __restrict__ h, const float* __restrict__ delta,
                          const float* __restrict__ gs, const float* __restrict__ gb) {
    __shared__ float sh[8];
    int row = blockIdx.x, tid = threadIdx.x;
    size_t base = (size_t)row * DD;
    float v[3];
    float sum = 0.f;
    #pragma unroll
    for (int t = 0; t < 3; t++) {
        int c = tid + t * 256;
        v[t] = h[base + c] + delta[base + c];
        sum += v[t];
    }
    float mean = block_reduce_sum(sum, sh) * (1.0f / 768.0f);
    float sq = 0.f;
    #pragma unroll
    for (int t = 0; t < 3; t++) { float d = v[t] - mean; sq += d * d; }
    float var = block_reduce_sum(sq, sh) * (1.0f / 768.0f);
    float inv = rsqrtf(var + 1e-5f);
    #pragma unroll
    for (int t = 0; t < 3; t++) {
        int c = tid + t * 256;
        h[base + c] = (v[t] - mean) * inv * gs[c] + gb[c];
    }
}

// ---------------- launcher ---------------------------------------------------
extern "C" void kernel_launch(void* const* d_in, const int* in_sizes, int n_in,
                              void* d_out, int out_size) {
    const int*   x     = (const int*)  d_in[0];
    const float* emb   = (const float*)d_in[1];
    const float* Wq    = (const float*)d_in[2];
    const float* Wk    = (const float*)d_in[3];
    const float* Wv    = (const float*)d_in[4];
    const float* Wo    = (const float*)d_in[5];
    const float* ln1_s = (const float*)d_in[6];
    const float* ln1_b = (const float*)d_in[7];
    const float* W1    = (const float*)d_in[8];
    const float* b1    = (const float*)d_in[9];
    const float* W2    = (const float*)d_in[10];
    const float* b2    = (const float*)d_in[11];
    const float* ln2_s = (const float*)d_in[12];
    const float* ln2_b = (const float*)d_in[13];
    const float* lm_W  = (const float*)d_in[14];
    const float* lm_b  = (const float*)d_in[15];
    float* out = (float*)d_out;

    float *h_, *q_, *k_, *v_, *av_, *tmp_, *ff_;
    cudaGetSymbolAddress((void**)&h_,   g_h);
    cudaGetSymbolAddress((void**)&q_,   g_q);
    cudaGetSymbolAddress((void**)&k_,   g_k);
    cudaGetSymbolAddress((void**)&v_,   g_v);
    cudaGetSymbolAddress((void**)&av_,  g_av);
    cudaGetSymbolAddress((void**)&tmp_, g_tmp);
    cudaGetSymbolAddress((void**)&ff_,  g_ff);

    cudaFuncSetAttribute(attn_kernel, cudaFuncAttributeMaxDynamicSharedMemorySize, ATTN_SMEM);

    embed_kernel<<<MM, 256>>>(x, emb, h_);

    dim3 gProj(DD / 128, MM / 128);     // (6,16)
    dim3 gFF1(DFFF / 128, MM / 128);    // (24,16)
    dim3 gLM(VV / 128, MM / 128);       // (250,16)
    dim3 gAttn(SS / 64, BB * HH);       // (16,24)

    for (int l = 0; l < LL; l++) {
        const float* Wq_l = Wq + (size_t)l * DD * (HH * DKK);
        const float* Wk_l = Wk + (size_t)l * DD * (HH * DKK);
        const float* Wv_l = Wv + (size_t)l * DD * (HH * DKK);
        const float* Wo_l = Wo + (size_t)l * (HH * DKK) * DD;
        const float* W1_l = W1 + (size_t)l * DD * DFFF;
        const float* W2_l = W2 + (size_t)l * DFFF * DD;

        gemm128<<<gProj, 256>>>(h_, Wq_l, nullptr, q_, DD, DD, 0);
        gemm128<<<gProj, 256>>>(h_, Wk_l, nullptr, k_, DD, DD, 0);
        gemm128<<<gProj, 256>>>(h_, Wv_l, nullptr, v_, DD, DD, 0);

        attn_kernel<<<gAttn, 256, ATTN_SMEM>>>(q_, k_, v_, av_);

        gemm128<<<gProj, 256>>>(av_, Wo_l, nullptr, tmp_, DD, DD, 0);
        ln_kernel<<<MM, 256>>>(h_, tmp_, ln1_s + (size_t)l * DD, ln1_b + (size_t)l * DD);

        gemm128<<<gFF1, 256>>>(h_, W1_l, b1 + (size_t)l * DFFF, ff_, DFFF, DD, 2);
        gemm128<<<gProj, 256>>>(ff_, W2_l, b2 + (size_t)l * DD, tmp_, DD, DFFF, 1);
        ln_kernel<<<MM, 256>>>(h_, tmp_, ln2_s + (size_t)l * DD, ln2_b + (size_t)l * DD);
    }

    gemm128<<<gLM, 256>>>(h_, lm_W, lm_b, out, VV, DD, 1);
}

// round 2
// speedup vs baseline: 2.3741x; 2.3741x over previous
#include <cuda_runtime.h>
#include <cuda_bf16.h>
#include <math.h>

// Problem constants
#define BB 2
#define SS 1024
#define DD 768
#define HH 12
#define DKK 64
#define DFFF 3072
#define VV 32000
#define LL 4
#define MM (BB*SS)   // 2048

// ---------------- scratch (static device globals; no allocation) -------------
__device__ float g_h  [MM*DD];
__device__ float g_q  [MM*DD];
__device__ float g_k  [MM*DD];
__device__ float g_v  [MM*DD];
__device__ float g_av [MM*DD];
__device__ float g_tmp[MM*DD];
__device__ float g_ff [MM*DFFF];

// ---------------- embedding + sinusoidal PE ---------------------------------
__global__ void embed_kernel(const int* __restrict__ x, const float* __restrict__ emb,
                             float* __restrict__ h) {
    int row = blockIdx.x;                 // b*S + s
    int s = row & (SS - 1);
    int tok = x[row];
    for (int c = threadIdx.x; c < DD; c += blockDim.x) {
        float ef = (float)(c & ~1) / (float)DD;
        float sc = powf(10000.0f, ef);
        float ang = (float)s / sc;
        float pe = (c & 1) ? cosf(ang) : sinf(ang);
        h[(size_t)row * DD + c] = emb[(size_t)tok * DD + c] + pe;
    }
}

// ---------------- tf32 tensor-core GEMM 128x128x32, cp.async 2-stage --------
// C[M,N] = A[M,K] @ B[K,N]   epi: 0=none, 1=+bias, 2=gelu(+bias)
__device__ __forceinline__ float gelu_exact(float x) {
    return 0.5f * x * (1.0f + erff(x * 0.7071067811865476f));
}

__device__ __forceinline__ unsigned f2tf(float f) {
    unsigned u;
    asm("cvt.rna.tf32.f32 %0, %1;" : "=r"(u) : "f"(f));
    return u;
}

__device__ __forceinline__ void mma_tf32(float c[4], const unsigned a[4], const unsigned b[2]) {
    asm volatile("mma.sync.aligned.m16n8k8.row.col.f32.tf32.tf32.f32 "
                 "{%0,%1,%2,%3},{%4,%5,%6,%7},{%8,%9},{%0,%1,%2,%3};"
                 : "+f"(c[0]), "+f"(c[1]), "+f"(c[2]), "+f"(c[3])
                 : "r"(a[0]), "r"(a[1]), "r"(a[2]), "r"(a[3]), "r"(b[0]), "r"(b[1]));
}

#define CPA16(dst, src) asm volatile("cp.async.cg.shared.global [%0], [%1], 16;" :: "r"(dst), "l"(src))

#define ASTR 36
#define BSTR 136
#define ABUF (128*ASTR)
#define BBUF (32*BSTR)
#define SMEM_GEMM ((2*ABUF + 2*BBUF) * 4)

__global__ __launch_bounds__(256)
void gemm_tf32(const float* __restrict__ A, const float* __restrict__ B,
               const float* __restrict__ bias, float* __restrict__ C,
               int N, int K, int epi)
{
    extern __shared__ float sm[];
    float* As = sm;              // [2][128][36]
    float* Bs = sm + 2 * ABUF;   // [2][32][136]

    int tid = threadIdx.x;
    int lane = tid & 31;
    int warp = tid >> 5;
    int g  = lane >> 2;   // 0..7
    int tg = lane & 3;    // 0..3
    int wm = warp >> 2;   // 0..1 : 64-row half
    int wn = warp & 3;    // 0..3 : 32-col quarter

    const float* Ab = A + (size_t)blockIdx.y * 128 * K;
    const float* Bb = B + (size_t)blockIdx.x * 128;

    float c[4][4][4];
    #pragma unroll
    for (int i = 0; i < 4; i++)
        #pragma unroll
        for (int j = 0; j < 4; j++)
            #pragma unroll
            for (int r = 0; r < 4; r++) c[i][j][r] = 0.f;

    const int T = K >> 5;

    auto load_tile = [&](int kt, int buf) {
        float* Ad = As + buf * ABUF;
        float* Bd = Bs + buf * BBUF;
        #pragma unroll
        for (int i = 0; i < 4; i++) {
            int id = tid + i * 256;            // 0..1023
            int r  = id >> 3;                  // 0..127
            int c4 = (id & 7) * 4;             // 0..28
            unsigned dst = (unsigned)__cvta_generic_to_shared(Ad + r * ASTR + c4);
            CPA16(dst, Ab + (size_t)r * K + kt + c4);
        }
        #pragma unroll
        for (int i = 0; i < 4; i++) {
            int id = tid + i * 256;            // 0..1023
            int r  = id >> 5;                  // 0..31
            int c4 = (id & 31) * 4;            // 0..124
            unsigned dst = (unsigned)__cvta_generic_to_shared(Bd + r * BSTR + c4);
            CPA16(dst, Bb + (size_t)(kt + r) * N + c4);
        }
    };

    load_tile(0, 0);
    asm volatile("cp.async.commit_group;");

    for (int t = 0; t < T; t++) {
        asm volatile("cp.async.wait_group 0;");
        __syncthreads();
        if (t + 1 < T) {
            load_tile((t + 1) * 32, (t + 1) & 1);
            asm volatile("cp.async.commit_group;");
        }

        const float* Af = As + (t & 1) * ABUF + wm * 64 * ASTR;
        const float* Bf = Bs + (t & 1) * BBUF + wn * 32;

        #pragma unroll
        for (int ks = 0; ks < 4; ks++) {
            int k0 = ks * 8;
            unsigned af[4][4], bf[4][2];
            #pragma unroll
            for (int mt = 0; mt < 4; mt++) {
                const float* ap = Af + (mt * 16 + g) * ASTR + k0 + tg;
                af[mt][0] = f2tf(ap[0]);
                af[mt][1] = f2tf(ap[8 * ASTR]);
                af[mt][2] = f2tf(ap[4]);
                af[mt][3] = f2tf(ap[8 * ASTR + 4]);
            }
            #pragma unroll
            for (int nt = 0; nt < 4; nt++) {
                const float* bp = Bf + (k0 + tg) * BSTR + nt * 8 + g;
                bf[nt][0] = f2tf(bp[0]);
                bf[nt][1] = f2tf(bp[4 * BSTR]);
            }
            #pragma unroll
            for (int mt = 0; mt < 4; mt++)
                #pragma unroll
                for (int nt = 0; nt < 4; nt++)
                    mma_tf32(c[mt][nt], af[mt], bf[nt]);
        }
        __syncthreads();
    }

    // epilogue
    int colg = blockIdx.x * 128 + wn * 32;
    int rowg = blockIdx.y * 128 + wm * 64;
    #pragma unroll
    for (int mt = 0; mt < 4; mt++) {
        #pragma unroll
        for (int half = 0; half < 2; half++) {
            int row = rowg + mt * 16 + g + half * 8;
            #pragma unroll
            for (int nt = 0; nt < 4; nt++) {
                int col = colg + nt * 8 + tg * 2;
                float v0 = c[mt][nt][half * 2 + 0];
                float v1 = c[mt][nt][half * 2 + 1];
                if (epi >= 1) { v0 += bias[col]; v1 += bias[col + 1]; }
                if (epi == 2) { v0 = gelu_exact(v0); v1 = gelu_exact(v1); }
                float2 w; w.x = v0; w.y = v1;
                *reinterpret_cast<float2*>(C + (size_t)row * N + col) = w;
            }
        }
    }
}

// ---------------- streaming causal attention (no-max custom softmax) --------
#define ATTN_SMEM ((3 * 64 * 65 + 64) * 4)

__global__ void attn_kernel(const float* __restrict__ q, const float* __restrict__ k,
                            const float* __restrict__ v, float* __restrict__ o) {
    extern __shared__ float sm[];
    float* qs    = sm;                 // [64][65]
    float* es    = sm + 64 * 65;       // K tile, reused as e tile
    float* vs    = sm + 2 * 64 * 65;   // [64][65]
    float* denom = sm + 3 * 64 * 65;   // [64]

    int qt = blockIdx.x;
    int bh = blockIdx.y;
    int b = bh / HH, hh = bh % HH;
    const float* qb = q + (size_t)b * SS * DD + hh * DKK;
    const float* kb = k + (size_t)b * SS * DD + hh * DKK;
    const float* vb = v + (size_t)b * SS * DD + hh * DKK;

    int tid = threadIdx.x;
    int tx = tid & 15, ty = tid >> 4;

    for (int idx = tid; idx < 64 * 64; idx += 256) {
        int r = idx >> 6, c = idx & 63;
        qs[r * 65 + c] = qb[(size_t)(qt * 64 + r) * DD + c];
    }
    if (tid < 64) denom[tid] = 0.f;
    float oacc[4][4];
    #pragma unroll
    for (int i = 0; i < 4; i++)
        #pragma unroll
        for (int j = 0; j < 4; j++) oacc[i][j] = 0.f;
    __syncthreads();

    for (int kt = 0; kt <= qt; kt++) {
        for (int idx = tid; idx < 64 * 64; idx += 256) {
            int r = idx >> 6, c = idx & 63;
            es[r * 65 + c] = kb[(size_t)(kt * 64 + r) * DD + c];
            vs[r * 65 + c] = vb[(size_t)(kt * 64 + r) * DD + c];
        }
        __syncthreads();

        float s[4][4];
        #pragma unroll
        for (int i = 0; i < 4; i++)
            #pragma unroll
            for (int j = 0; j < 4; j++) s[i][j] = 0.f;
        #pragma unroll 8
        for (int d = 0; d < 64; d++) {
            float aq[4], ak[4];
            #pragma unroll
            for (int i = 0; i < 4; i++) aq[i] = qs[(ty * 4 + i) * 65 + d];
            #pragma unroll
            for (int j = 0; j < 4; j++) ak[j] = es[(tx * 4 + j) * 65 + d];
            #pragma unroll
            for (int i = 0; i < 4; i++)
                #pragma unroll
                for (int j = 0; j < 4; j++) s[i][j] += aq[i] * ak[j];
        }
        __syncthreads();

        #pragma unroll
        for (int i = 0; i < 4; i++) {
            int qg = qt * 64 + ty * 4 + i;
            float rs = 0.f;
            #pragma unroll
            for (int j = 0; j < 4; j++) {
                int kg = kt * 64 + tx * 4 + j;
                float e = (kg < qg) ? expf(s[i][j] * 0.125f) : 0.f;
                es[(ty * 4 + i) * 65 + (tx * 4 + j)] = e;
                rs += e;
            }
            atomicAdd(&denom[ty * 4 + i], rs);
        }
        __syncthreads();

        #pragma unroll 4
        for (int kk = 0; kk < 64; kk++) {
            float ef[4], vf[4];
            #pragma unroll
            for (int i = 0; i < 4; i++) ef[i] = es[(ty * 4 + i) * 65 + kk];
            #pragma unroll
            for (int j = 0; j < 4; j++) vf[j] = vs[kk * 65 + tx * 4 + j];
            #pragma unroll
            for (int i = 0; i < 4; i++)
                #pragma unroll
                for (int j = 0; j < 4; j++) oacc[i][j] += ef[i] * vf[j];
        }
        __syncthreads();
    }

    #pragma unroll
    for (int i = 0; i < 4; i++) {
        int qg = qt * 64 + ty * 4 + i;
        float dn = denom[ty * 4 + i] + 1e-9f;
        #pragma unroll
        for (int j = 0; j < 4; j++)
            o[(size_t)(b * SS + qg) * DD + hh * DKK + tx * 4 + j] = oacc[i][j] / dn;
    }
}

// ---------------- fused residual-add + LayerNorm (in-place on h) ------------
__device__ __forceinline__ float block_reduce_sum(float v, float* sh) {
    int tid = threadIdx.x;
    #pragma unroll
    for (int o = 16; o; o >>= 1) v += __shfl_xor_sync(0xffffffffu, v, o);
    if ((tid & 31) == 0) sh[tid >> 5] = v;
    __syncthreads();
    float r = 0.f;
    if (tid < 8) r = sh[tid];
    if (tid < 32) {
        #pragma unroll
        for (int o = 4; o; o >>= 1) r += __shfl_xor_sync(0xffffffffu, r, o);
    }
    if (tid == 0) sh[0] = r;
    __syncthreads();
    float out = sh[0];
    __syncthreads();
    return out;
}

__global__ void ln_kernel(float* __restrict__ h, const float* __restrict__ delta,
                          const float* __restrict__ gs, const float* __restrict__ gb) {
    __shared__ float sh[8];
    int row = blockIdx.x, tid = threadIdx.x;
    size_t base = (size_t)row * DD;
    float v[3];
    float sum = 0.f;
    #pragma unroll
    for (int t = 0; t < 3; t++) {
        int c = tid + t * 256;
        v[t] = h[base + c] + delta[base + c];
        sum += v[t];
    }
    float mean = block_reduce_sum(sum, sh) * (1.0f / 768.0f);
    float sq = 0.f;
    #pragma unroll
    for (int t = 0; t < 3; t++) { float d = v[t] - mean; sq += d * d; }
    float var = block_reduce_sum(sq, sh) * (1.0f / 768.0f);
    float inv = rsqrtf(var + 1e-5f);
    #pragma unroll
    for (int t = 0; t < 3; t++) {
        int c = tid + t * 256;
        h[base + c] = (v[t] - mean) * inv * gs[c] + gb[c];
    }
}

// ---------------- launcher ---------------------------------------------------
extern "C" void kernel_launch(void* const* d_in, const int* in_sizes, int n_in,
                              void* d_out, int out_size) {
    const int*   x     = (const int*)  d_in[0];
    const float* emb   = (const float*)d_in[1];
    const float* Wq    = (const float*)d_in[2];
    const float* Wk    = (const float*)d_in[3];
    const float* Wv    = (const float*)d_in[4];
    const float* Wo    = (const float*)d_in[5];
    const float* ln1_s = (const float*)d_in[6];
    const float* ln1_b = (const float*)d_in[7];
    const float* W1    = (const float*)d_in[8];
    const float* b1    = (const float*)d_in[9];
    const float* W2    = (const float*)d_in[10];
    const float* b2    = (const float*)d_in[11];
    const float* ln2_s = (const float*)d_in[12];
    const float* ln2_b = (const float*)d_in[13];
    const float* lm_W  = (const float*)d_in[14];
    const float* lm_b  = (const float*)d_in[15];
    float* out = (float*)d_out;

    float *h_, *q_, *k_, *v_, *av_, *tmp_, *ff_;
    cudaGetSymbolAddress((void**)&h_,   g_h);
    cudaGetSymbolAddress((void**)&q_,   g_q);
    cudaGetSymbolAddress((void**)&k_,   g_k);
    cudaGetSymbolAddress((void**)&v_,   g_v);
    cudaGetSymbolAddress((void**)&av_,  g_av);
    cudaGetSymbolAddress((void**)&tmp_, g_tmp);
    cudaGetSymbolAddress((void**)&ff_,  g_ff);

    cudaFuncSetAttribute(attn_kernel, cudaFuncAttributeMaxDynamicSharedMemorySize, ATTN_SMEM);
    cudaFuncSetAttribute(gemm_tf32, cudaFuncAttributeMaxDynamicSharedMemorySize, SMEM_GEMM);

    embed_kernel<<<MM, 256>>>(x, emb, h_);

    dim3 gProj(DD / 128, MM / 128);     // (6,16)
    dim3 gFF1(DFFF / 128, MM / 128);    // (24,16)
    dim3 gLM(VV / 128, MM / 128);       // (250,16)
    dim3 gAttn(SS / 64, BB * HH);       // (16,24)

    for (int l = 0; l < LL; l++) {
        const float* Wq_l = Wq + (size_t)l * DD * (HH * DKK);
        const float* Wk_l = Wk + (size_t)l * DD * (HH * DKK);
        const float* Wv_l = Wv + (size_t)l * DD * (HH * DKK);
        const float* Wo_l = Wo + (size_t)l * (HH * DKK) * DD;
        const float* W1_l = W1 + (size_t)l * DD * DFFF;
        const float* W2_l = W2 + (size_t)l * DFFF * DD;

        gemm_tf32<<<gProj, 256, SMEM_GEMM>>>(h_, Wq_l, nullptr, q_, DD, DD, 0);
        gemm_tf32<<<gProj, 256, SMEM_GEMM>>>(h_, Wk_l, nullptr, k_, DD, DD, 0);
        gemm_tf32<<<gProj, 256, SMEM_GEMM>>>(h_, Wv_l, nullptr, v_, DD, DD, 0);

        attn_kernel<<<gAttn, 256, ATTN_SMEM>>>(q_, k_, v_, av_);

        gemm_tf32<<<gProj, 256, SMEM_GEMM>>>(av_, Wo_l, nullptr, tmp_, DD, DD, 0);
        ln_kernel<<<MM, 256>>>(h_, tmp_, ln1_s + (size_t)l * DD, ln1_b + (size_t)l * DD);

        gemm_tf32<<<gFF1, 256, SMEM_GEMM>>>(h_, W1_l, b1 + (size_t)l * DFFF, ff_, DFFF, DD, 2);
        gemm_tf32<<<gProj, 256, SMEM_GEMM>>>(ff_, W2_l, b2 + (size_t)l * DD, tmp_, DD, DFFF, 1);
        ln_kernel<<<MM, 256>>>(h_, tmp_, ln2_s + (size_t)l * DD, ln2_b + (size_t)l * DD);
    }

    gemm_tf32<<<gLM, 256, SMEM_GEMM>>>(h_, lm_W, lm_b, out, VV, DD, 1);
}

// round 3
// speedup vs baseline: 2.5087x; 1.0567x over previous
#include <cuda_runtime.h>
#include <cuda_bf16.h>
#include <math.h>

// Problem constants
#define BB 2
#define SS 1024
#define DD 768
#define HH 12
#define DKK 64
#define DFFF 3072
#define VV 32000
#define LL 4
#define MM (BB*SS)   // 2048

// ---------------- scratch (static device globals; no allocation) -------------
__device__ float g_h  [MM*DD];
__device__ float g_q  [MM*DD];
__device__ float g_k  [MM*DD];
__device__ float g_v  [MM*DD];
__device__ float g_av [MM*DD];
__device__ float g_tmp[MM*DD];
__device__ float g_ff [MM*DFFF];

// ---------------- embedding + sinusoidal PE ---------------------------------
__global__ void embed_kernel(const int* __restrict__ x, const float* __restrict__ emb,
                             float* __restrict__ h) {
    int row = blockIdx.x;
    int s = row & (SS - 1);
    int tok = x[row];
    for (int c = threadIdx.x; c < DD; c += blockDim.x) {
        float ef = (float)(c & ~1) / (float)DD;
        float sc = powf(10000.0f, ef);
        float ang = (float)s / sc;
        float pe = (c & 1) ? cosf(ang) : sinf(ang);
        h[(size_t)row * DD + c] = emb[(size_t)tok * DD + c] + pe;
    }
}

// ---------------- tf32 tensor-core GEMM, cp.async 2-stage --------------------
__device__ __forceinline__ float gelu_exact(float x) {
    return 0.5f * x * (1.0f + erff(x * 0.7071067811865476f));
}

__device__ __forceinline__ unsigned f2tf(float f) {
    unsigned u;
    asm("cvt.rna.tf32.f32 %0, %1;" : "=r"(u) : "f"(f));
    return u;
}

__device__ __forceinline__ void mma_tf32(float c[4], const unsigned a[4], const unsigned b[2]) {
    asm volatile("mma.sync.aligned.m16n8k8.row.col.f32.tf32.tf32.f32 "
                 "{%0,%1,%2,%3},{%4,%5,%6,%7},{%8,%9},{%0,%1,%2,%3};"
                 : "+f"(c[0]), "+f"(c[1]), "+f"(c[2]), "+f"(c[3])
                 : "r"(a[0]), "r"(a[1]), "r"(a[2]), "r"(a[3]), "r"(b[0]), "r"(b[1]));
}

#define CPA16(dst, src) asm volatile("cp.async.cg.shared.global [%0], [%1], 16;" :: "r"(dst), "l"(src))

#define ASTR 36
#define BSTR 136
#define BBUF (32*BSTR)
#define SMEM_GEMM_BYTES(BM) ((2*(BM)*ASTR + 2*BBUF) * 4)

// BM x 128 x 32 tile; 8 warps: wm over 2 row-halves, wn over 4 col-quarters.
template<int BM>
__device__ __forceinline__ void gemm_body(
    const float* __restrict__ A, const float* __restrict__ B,
    const float* __restrict__ bias, float* __restrict__ C,
    int N, int K, int epi, int bx, int by, float* sm)
{
    constexpr int MT   = BM / 32;         // 16-row subtiles per warp
    constexpr int ABUF = BM * ASTR;

    float* As = sm;               // [2][BM][ASTR]
    float* Bs = sm + 2 * ABUF;    // [2][32][BSTR]

    int tid = threadIdx.x;
    int lane = tid & 31;
    int warp = tid >> 5;
    int g  = lane >> 2;
    int tg = lane & 3;
    int wm = warp >> 2;   // 0..1
    int wn = warp & 3;    // 0..3

    const float* Ab = A + (size_t)by * BM * K;
    const float* Bb = B + (size_t)bx * 128;

    float c[MT][4][4];
    #pragma unroll
    for (int i = 0; i < MT; i++)
        #pragma unroll
        for (int j = 0; j < 4; j++)
            #pragma unroll
            for (int r = 0; r < 4; r++) c[i][j][r] = 0.f;

    const int T = K >> 5;

    auto load_tile = [&](int kt, int buf) {
        float* Ad = As + buf * ABUF;
        float* Bd = Bs + buf * BBUF;
        #pragma unroll
        for (int i = 0; i < BM / 32; i++) {
            int id = tid + i * 256;
            int r  = id >> 3;
            int c4 = (id & 7) * 4;
            unsigned dst = (unsigned)__cvta_generic_to_shared(Ad + r * ASTR + c4);
            CPA16(dst, Ab + (size_t)r * K + kt + c4);
        }
        #pragma unroll
        for (int i = 0; i < 4; i++) {
            int id = tid + i * 256;
            int r  = id >> 5;
            int c4 = (id & 31) * 4;
            unsigned dst = (unsigned)__cvta_generic_to_shared(Bd + r * BSTR + c4);
            CPA16(dst, Bb + (size_t)(kt + r) * N + c4);
        }
    };

    load_tile(0, 0);
    asm volatile("cp.async.commit_group;");

    for (int t = 0; t < T; t++) {
        asm volatile("cp.async.wait_group 0;");
        __syncthreads();
        if (t + 1 < T) {
            load_tile((t + 1) * 32, (t + 1) & 1);
            asm volatile("cp.async.commit_group;");
        }

        const float* Af = As + (t & 1) * ABUF + wm * (BM / 2) * ASTR;
        const float* Bf = Bs + (t & 1) * BBUF + wn * 32;

        #pragma unroll
        for (int ks = 0; ks < 4; ks++) {
            int k0 = ks * 8;
            unsigned af[MT][4], bf[4][2];
            #pragma unroll
            for (int mt = 0; mt < MT; mt++) {
                const float* ap = Af + (mt * 16 + g) * ASTR + k0 + tg;
                af[mt][0] = f2tf(ap[0]);
                af[mt][1] = f2tf(ap[8 * ASTR]);
                af[mt][2] = f2tf(ap[4]);
                af[mt][3] = f2tf(ap[8 * ASTR + 4]);
            }
            #pragma unroll
            for (int nt = 0; nt < 4; nt++) {
                const float* bp = Bf + (k0 + tg) * BSTR + nt * 8 + g;
                bf[nt][0] = f2tf(bp[0]);
                bf[nt][1] = f2tf(bp[4 * BSTR]);
            }
            #pragma unroll
            for (int mt = 0; mt < MT; mt++)
                #pragma unroll
                for (int nt = 0; nt < 4; nt++)
                    mma_tf32(c[mt][nt], af[mt], bf[nt]);
        }
        __syncthreads();
    }

    int colg = bx * 128 + wn * 32;
    int rowg = by * BM + wm * (BM / 2);
    #pragma unroll
    for (int mt = 0; mt < MT; mt++) {
        #pragma unroll
        for (int half = 0; half < 2; half++) {
            int row = rowg + mt * 16 + g + half * 8;
            #pragma unroll
            for (int nt = 0; nt < 4; nt++) {
                int col = colg + nt * 8 + tg * 2;
                float v0 = c[mt][nt][half * 2 + 0];
                float v1 = c[mt][nt][half * 2 + 1];
                if (epi >= 1) { v0 += bias[col]; v1 += bias[col + 1]; }
                if (epi == 2) { v0 = gelu_exact(v0); v1 = gelu_exact(v1); }
                float2 w; w.x = v0; w.y = v1;
                *reinterpret_cast<float2*>(C + (size_t)row * N + col) = w;
            }
        }
    }
}

template<int BM>
__global__ __launch_bounds__(256, 2)
void gemm_tf32(const float* __restrict__ A, const float* __restrict__ B,
               const float* __restrict__ bias, float* __restrict__ C,
               int N, int K, int epi)
{
    extern __shared__ float sm[];
    gemm_body<BM>(A, B, bias, C, N, K, epi, blockIdx.x, blockIdx.y, sm);
}

// merged QKV: grid.x = 18 (3 weights x 6 col tiles), grid.y = 16
__global__ __launch_bounds__(256, 2)
void qkv_gemm(const float* __restrict__ h,
              const float* __restrict__ Wq, const float* __restrict__ Wk,
              const float* __restrict__ Wv,
              float* __restrict__ q, float* __restrict__ k, float* __restrict__ v)
{
    extern __shared__ float sm[];
    int which = blockIdx.x / 6;
    int bx = blockIdx.x % 6;
    const float* W = (which == 0) ? Wq : (which == 1) ? Wk : Wv;
    float* C = (which == 0) ? q : (which == 1) ? k : v;
    gemm_body<128>(h, W, nullptr, C, DD, DD, 0, bx, blockIdx.y, sm);
}

// ---------------- streaming causal attention (no-max custom softmax) --------
#define ATTN_SMEM ((3 * 64 * 65 + 64) * 4)

__global__ void attn_kernel(const float* __restrict__ q, const float* __restrict__ k,
                            const float* __restrict__ v, float* __restrict__ o) {
    extern __shared__ float sm[];
    float* qs    = sm;
    float* es    = sm + 64 * 65;
    float* vs    = sm + 2 * 64 * 65;
    float* denom = sm + 3 * 64 * 65;

    int qt = blockIdx.x;
    int bh = blockIdx.y;
    int b = bh / HH, hh = bh % HH;
    const float* qb = q + (size_t)b * SS * DD + hh * DKK;
    const float* kb = k + (size_t)b * SS * DD + hh * DKK;
    const float* vb = v + (size_t)b * SS * DD + hh * DKK;

    int tid = threadIdx.x;
    int tx = tid & 15, ty = tid >> 4;

    for (int idx = tid; idx < 64 * 64; idx += 256) {
        int r = idx >> 6, c = idx & 63;
        qs[r * 65 + c] = qb[(size_t)(qt * 64 + r) * DD + c];
    }
    if (tid < 64) denom[tid] = 0.f;
    float oacc[4][4];
    #pragma unroll
    for (int i = 0; i < 4; i++)
        #pragma unroll
        for (int j = 0; j < 4; j++) oacc[i][j] = 0.f;
    __syncthreads();

    for (int kt = 0; kt <= qt; kt++) {
        for (int idx = tid; idx < 64 * 64; idx += 256) {
            int r = idx >> 6, c = idx & 63;
            es[r * 65 + c] = kb[(size_t)(kt * 64 + r) * DD + c];
            vs[r * 65 + c] = vb[(size_t)(kt * 64 + r) * DD + c];
        }
        __syncthreads();

        float s[4][4];
        #pragma unroll
        for (int i = 0; i < 4; i++)
            #pragma unroll
            for (int j = 0; j < 4; j++) s[i][j] = 0.f;
        #pragma unroll 8
        for (int d = 0; d < 64; d++) {
            float aq[4], ak[4];
            #pragma unroll
            for (int i = 0; i < 4; i++) aq[i] = qs[(ty * 4 + i) * 65 + d];
            #pragma unroll
            for (int j = 0; j < 4; j++) ak[j] = es[(tx * 4 + j) * 65 + d];
            #pragma unroll
            for (int i = 0; i < 4; i++)
                #pragma unroll
                for (int j = 0; j < 4; j++) s[i][j] += aq[i] * ak[j];
        }
        __syncthreads();

        #pragma unroll
        for (int i = 0; i < 4; i++) {
            int qg = qt * 64 + ty * 4 + i;
            float rs = 0.f;
            #pragma unroll
            for (int j = 0; j < 4; j++) {
                int kg = kt * 64 + tx * 4 + j;
                float e = (kg < qg) ? expf(s[i][j] * 0.125f) : 0.f;
                es[(ty * 4 + i) * 65 + (tx * 4 + j)] = e;
                rs += e;
            }
            atomicAdd(&denom[ty * 4 + i], rs);
        }
        __syncthreads();

        #pragma unroll 4
        for (int kk = 0; kk < 64; kk++) {
            float ef[4], vf[4];
            #pragma unroll
            for (int i = 0; i < 4; i++) ef[i] = es[(ty * 4 + i) * 65 + kk];
            #pragma unroll
            for (int j = 0; j < 4; j++) vf[j] = vs[kk * 65 + tx * 4 + j];
            #pragma unroll
            for (int i = 0; i < 4; i++)
                #pragma unroll
                for (int j = 0; j < 4; j++) oacc[i][j] += ef[i] * vf[j];
        }
        __syncthreads();
    }

    #pragma unroll
    for (int i = 0; i < 4; i++) {
        int qg = qt * 64 + ty * 4 + i;
        float dn = denom[ty * 4 + i] + 1e-9f;
        #pragma unroll
        for (int j = 0; j < 4; j++)
            o[(size_t)(b * SS + qg) * DD + hh * DKK + tx * 4 + j] = oacc[i][j] / dn;
    }
}

// ---------------- fused residual-add + LayerNorm (in-place on h) ------------
__device__ __forceinline__ float block_reduce_sum(float v, float* sh) {
    int tid = threadIdx.x;
    #pragma unroll
    for (int o = 16; o; o >>= 1) v += __shfl_xor_sync(0xffffffffu, v, o);
    if ((tid & 31) == 0) sh[tid >> 5] = v;
    __syncthreads();
    float r = 0.f;
    if (tid < 8) r = sh[tid];
    if (tid < 32) {
        #pragma unroll
        for (int o = 4; o; o >>= 1) r += __shfl_xor_sync(0xffffffffu, r, o);
    }
    if (tid == 0) sh[0] = r;
    __syncthreads();
    float out = sh[0];
    __syncthreads();
    return out;
}

__global__ void ln_kernel(float* __restrict__ h, const float* __restrict__ delta,
                          const float* __restrict__ gs, const float* __restrict__ gb) {
    __shared__ float sh[8];
    int row = blockIdx.x, tid = threadIdx.x;
    size_t base = (size_t)row * DD;
    float v[3];
    float sum = 0.f;
    #pragma unroll
    for (int t = 0; t < 3; t++) {
        int c = tid + t * 256;
        v[t] = h[base + c] + delta[base + c];
        sum += v[t];
    }
    float mean = block_reduce_sum(sum, sh) * (1.0f / 768.0f);
    float sq = 0.f;
    #pragma unroll
    for (int t = 0; t < 3; t++) { float d = v[t] - mean; sq += d * d; }
    float var = block_reduce_sum(sq, sh) * (1.0f / 768.0f);
    float inv = rsqrtf(var + 1e-5f);
    #pragma unroll
    for (int t = 0; t < 3; t++) {
        int c = tid + t * 256;
        h[base + c] = (v[t] - mean) * inv * gs[c] + gb[c];
    }
}

// ---------------- launcher ---------------------------------------------------
extern "C" void kernel_launch(void* const* d_in, const int* in_sizes, int n_in,
                              void* d_out, int out_size) {
    const int*   x     = (const int*)  d_in[0];
    const float* emb   = (const float*)d_in[1];
    const float* Wq    = (const float*)d_in[2];
    const float* Wk    = (const float*)d_in[3];
    const float* Wv    = (const float*)d_in[4];
    const float* Wo    = (const float*)d_in[5];
    const float* ln1_s = (const float*)d_in[6];
    const float* ln1_b = (const float*)d_in[7];
    const float* W1    = (const float*)d_in[8];
    const float* b1    = (const float*)d_in[9];
    const float* W2    = (const float*)d_in[10];
    const float* b2    = (const float*)d_in[11];
    const float* ln2_s = (const float*)d_in[12];
    const float* ln2_b = (const float*)d_in[13];
    const float* lm_W  = (const float*)d_in[14];
    const float* lm_b  = (const float*)d_in[15];
    float* out = (float*)d_out;

    float *h_, *q_, *k_, *v_, *av_, *tmp_, *ff_;
    cudaGetSymbolAddress((void**)&h_,   g_h);
    cudaGetSymbolAddress((void**)&q_,   g_q);
    cudaGetSymbolAddress((void**)&k_,   g_k);
    cudaGetSymbolAddress((void**)&v_,   g_v);
    cudaGetSymbolAddress((void**)&av_,  g_av);
    cudaGetSymbolAddress((void**)&tmp_, g_tmp);
    cudaGetSymbolAddress((void**)&ff_,  g_ff);

    const int SM128 = SMEM_GEMM_BYTES(128);
    const int SM64  = SMEM_GEMM_BYTES(64);
    cudaFuncSetAttribute(attn_kernel, cudaFuncAttributeMaxDynamicSharedMemorySize, ATTN_SMEM);
    cudaFuncSetAttribute(gemm_tf32<128>, cudaFuncAttributeMaxDynamicSharedMemorySize, SM128);
    cudaFuncSetAttribute(gemm_tf32<64>,  cudaFuncAttributeMaxDynamicSharedMemorySize, SM64);
    cudaFuncSetAttribute(qkv_gemm, cudaFuncAttributeMaxDynamicSharedMemorySize, SM128);

    embed_kernel<<<MM, 256>>>(x, emb, h_);

    dim3 gQKV(18, MM / 128);            // (18,16) merged QKV
    dim3 gN768(DD / 128, MM / 64);      // (6,32)  BM=64 variant
    dim3 gFF1(DFFF / 128, MM / 128);    // (24,16)
    dim3 gLM(VV / 128, MM / 128);       // (250,16)
    dim3 gAttn(SS / 64, BB * HH);       // (16,24)

    for (int l = 0; l < LL; l++) {
        const float* Wq_l = Wq + (size_t)l * DD * (HH * DKK);
        const float* Wk_l = Wk + (size_t)l * DD * (HH * DKK);
        const float* Wv_l = Wv + (size_t)l * DD * (HH * DKK);
        const float* Wo_l = Wo + (size_t)l * (HH * DKK) * DD;
        const float* W1_l = W1 + (size_t)l * DD * DFFF;
        const float* W2_l = W2 + (size_t)l * DFFF * DD;

        qkv_gemm<<<gQKV, 256, SM128>>>(h_, Wq_l, Wk_l, Wv_l, q_, k_, v_);

        attn_kernel<<<gAttn, 256, ATTN_SMEM>>>(q_, k_, v_, av_);

        gemm_tf32<64><<<gN768, 256, SM64>>>(av_, Wo_l, nullptr, tmp_, DD, DD, 0);
        ln_kernel<<<MM, 256>>>(h_, tmp_, ln1_s + (size_t)l * DD, ln1_b + (size_t)l * DD);

        gemm_tf32<128><<<gFF1, 256, SM128>>>(h_, W1_l, b1 + (size_t)l * DFFF, ff_, DFFF, DD, 2);
        gemm_tf32<64><<<gN768, 256, SM64>>>(ff_, W2_l, b2 + (size_t)l * DD, tmp_, DD, DFFF, 1);
        ln_kernel<<<MM, 256>>>(h_, tmp_, ln2_s + (size_t)l * DD, ln2_b + (size_t)l * DD);
    }

    gemm_tf32<128><<<gLM, 256, SM128>>>(h_, lm_W, lm_b, out, VV, DD, 1);
}

// round 4
// speedup vs baseline: 3.3521x; 1.3362x over previous
#include <cuda_runtime.h>
#include <cuda_fp16.h>
#include <math.h>

// Problem constants
#define BB 2
#define SS 1024
#define DD 768
#define HH 12
#define DKK 64
#define DFFF 3072
#define VV 32000
#define LL 4
#define MM (BB*SS)       // 2048
#define NQKV (3*DD)      // 2304

// ---------------- scratch (static device globals; no allocation) -------------
__device__ float  g_h   [MM*DD];
__device__ float  g_qkv [MM*NQKV];
__device__ float  g_tmp [MM*DD];
__device__ __half g_h16 [MM*DD];
__device__ __half g_av16[MM*DD];
__device__ __half g_ff16[MM*DFFF];
// fp16 weights
__device__ __half g_wqkv16[LL*DD*NQKV];   // packed [l][k][which*768+n]
__device__ __half g_wo16  [LL*DD*DD];
__device__ __half g_w116  [LL*DD*DFFF];
__device__ __half g_w216  [LL*DFFF*DD];
__device__ __half g_lm16  [DD*VV];

// ---------------- fp32 -> fp16 conversion ------------------------------------
__global__ void f32_to_f16(const float* __restrict__ src, __half2* __restrict__ dst, int n4) {
    int i = blockIdx.x * blockDim.x + threadIdx.x;
    if (i < n4) {
        float4 v = reinterpret_cast<const float4*>(src)[i];
        dst[2 * i + 0] = __floats2half2_rn(v.x, v.y);
        dst[2 * i + 1] = __floats2half2_rn(v.z, v.w);
    }
}

// pack Wq/Wk/Wv (each [L][768][768]) into [L][768][2304] fp16
__global__ void qkv_pack(const float* __restrict__ Wq, const float* __restrict__ Wk,
                         const float* __restrict__ Wv, __half2* __restrict__ dst, int n4) {
    int i = blockIdx.x * blockDim.x + threadIdx.x;   // quad index
    if (i >= n4) return;
    int e = i * 4;
    int c = e % NQKV;
    int k = (e / NQKV) % DD;
    int l = e / (NQKV * DD);
    int which = c / DD;
    int n = c % DD;
    const float* W = (which == 0) ? Wq : (which == 1) ? Wk : Wv;
    float4 v = *reinterpret_cast<const float4*>(W + (size_t)l * DD * DD + (size_t)k * DD + n);
    dst[2 * i + 0] = __floats2half2_rn(v.x, v.y);
    dst[2 * i + 1] = __floats2half2_rn(v.z, v.w);
}

// ---------------- embedding + sinusoidal PE ----------------------------------
__global__ void embed_kernel(const int* __restrict__ x, const float* __restrict__ emb,
                             float* __restrict__ h, __half* __restrict__ h16) {
    int row = blockIdx.x;
    int s = row & (SS - 1);
    int tok = x[row];
    for (int c = threadIdx.x; c < DD; c += blockDim.x) {
        float ef = (float)(c & ~1) / (float)DD;
        float sc = powf(10000.0f, ef);
        float ang = (float)s / sc;
        float pe = (c & 1) ? cosf(ang) : sinf(ang);
        float v = emb[(size_t)tok * DD + c] + pe;
        h[(size_t)row * DD + c] = v;
        h16[(size_t)row * DD + c] = __float2half(v);
    }
}

// ---------------- fp16 tensor-core GEMM (ldmatrix + m16n8k16) ----------------
__device__ __forceinline__ float gelu_exact(float x) {
    return 0.5f * x * (1.0f + erff(x * 0.7071067811865476f));
}

#define CPA16(dst, src) asm volatile("cp.async.cg.shared.global [%0], [%1], 16;" :: "r"(dst), "l"(src))
#define LDSM4(r0,r1,r2,r3,addr) \
    asm volatile("ldmatrix.sync.aligned.m8n8.x4.shared.b16 {%0,%1,%2,%3},[%4];" \
                 : "=r"(r0),"=r"(r1),"=r"(r2),"=r"(r3) : "r"(addr))
#define LDSM4T(r0,r1,r2,r3,addr) \
    asm volatile("ldmatrix.sync.aligned.m8n8.x4.trans.shared.b16 {%0,%1,%2,%3},[%4];" \
                 : "=r"(r0),"=r"(r1),"=r"(r2),"=r"(r3) : "r"(addr))

__device__ __forceinline__ void mma16816(float c[4], const unsigned a[4], const unsigned b[2]) {
    asm volatile("mma.sync.aligned.m16n8k16.row.col.f32.f16.f16.f32 "
                 "{%0,%1,%2,%3},{%4,%5,%6,%7},{%8,%9},{%0,%1,%2,%3};"
                 : "+f"(c[0]), "+f"(c[1]), "+f"(c[2]), "+f"(c[3])
                 : "r"(a[0]), "r"(a[1]), "r"(a[2]), "r"(a[3]), "r"(b[0]), "r"(b[1]));
}

#define ASTR 40     // halves, pad 8 (row = 80B, banks stride 20 mod 32: conflict-free)
#define BSTR 136    // halves, pad 8 (row = 272B, banks stride 4 mod 32: conflict-free)
#define BBUF_H (32*BSTR)
#define SMEM_GEMM_BYTES(BM) ((2*(BM)*ASTR + 2*BBUF_H) * 2)

// BM x 128 x 32 tiles, 8 warps (wm: 2 row halves, wn: 4 col quarters)
template<int BM, typename OutT>
__device__ __forceinline__ void gemm_body(
    const __half* __restrict__ A, const __half* __restrict__ B,
    const float* __restrict__ bias, OutT* __restrict__ C,
    int N, int K, int epi, int bx, int by, __half* sm)
{
    constexpr int MT = BM / 32;
    constexpr int ABUF_H = BM * ASTR;

    __half* As = sm;
    __half* Bs = sm + 2 * ABUF_H;

    int tid = threadIdx.x;
    int lane = tid & 31;
    int warp = tid >> 5;
    int wm = warp >> 2;   // 0..1
    int wn = warp & 3;    // 0..3
    int g  = lane >> 2;
    int tg = lane & 3;

    const __half* Ab = A + (size_t)by * BM * K;
    const __half* Bb = B + (size_t)bx * 128;

    float c[MT][4][4];
    #pragma unroll
    for (int i = 0; i < MT; i++)
        #pragma unroll
        for (int j = 0; j < 4; j++)
            #pragma unroll
            for (int r = 0; r < 4; r++) c[i][j][r] = 0.f;

    const int T = K >> 5;

    auto load_tile = [&](int kt, int buf) {
        __half* Ad = As + buf * ABUF_H;
        __half* Bd = Bs + buf * BBUF_H;
        // A: BM*32 halves = BM*4 segments of 8 halves(16B)
        #pragma unroll
        for (int i = 0; i < BM / 64; i++) {
            int s = tid + i * 256;          // 0 .. BM*4-1
            int r  = s >> 2;
            int k8 = (s & 3) * 8;
            unsigned dst = (unsigned)__cvta_generic_to_shared(Ad + r * ASTR + k8);
            CPA16(dst, Ab + (size_t)r * K + kt + k8);
        }
        // B: 32*128 halves = 512 segments
        #pragma unroll
        for (int i = 0; i < 2; i++) {
            int s = tid + i * 256;          // 0..511
            int r  = s >> 4;
            int n8 = (s & 15) * 8;
            unsigned dst = (unsigned)__cvta_generic_to_shared(Bd + r * BSTR + n8);
            CPA16(dst, Bb + (size_t)(kt + r) * N + n8);
        }
    };

    load_tile(0, 0);
    asm volatile("cp.async.commit_group;");

    // per-thread ldmatrix base addresses (bytes)
    unsigned aBase = (unsigned)__cvta_generic_to_shared(
        As + (wm * (BM / 2) + (lane & 15)) * ASTR + (lane >> 4) * 8);
    unsigned bBase = (unsigned)__cvta_generic_to_shared(
        Bs + (lane & 15) * BSTR + wn * 32 + (lane >> 4) * 8);

    for (int t = 0; t < T; t++) {
        asm volatile("cp.async.wait_group 0;");
        __syncthreads();
        if (t + 1 < T) {
            load_tile((t + 1) * 32, (t + 1) & 1);
            asm volatile("cp.async.commit_group;");
        }

        unsigned aB = aBase + (t & 1) * (ABUF_H * 2);
        unsigned bB = bBase + (t & 1) * (BBUF_H * 2);

        #pragma unroll
        for (int kb = 0; kb < 2; kb++) {
            unsigned a[MT][4], b[4][2];
            #pragma unroll
            for (int mt = 0; mt < MT; mt++) {
                LDSM4(a[mt][0], a[mt][1], a[mt][2], a[mt][3],
                      aB + (mt * 16 * ASTR + kb * 16) * 2);
            }
            #pragma unroll
            for (int nb = 0; nb < 2; nb++) {
                unsigned t0, t1, t2, t3;
                LDSM4T(t0, t1, t2, t3, bB + (kb * 16 * BSTR + nb * 16) * 2);
                b[2 * nb][0] = t0; b[2 * nb][1] = t1;
                b[2 * nb + 1][0] = t2; b[2 * nb + 1][1] = t3;
            }
            #pragma unroll
            for (int mt = 0; mt < MT; mt++)
                #pragma unroll
                for (int j = 0; j < 4; j++)
                    mma16816(c[mt][j], a[mt], b[j]);
        }
        __syncthreads();
    }

    // epilogue: lane mapping m16n8 -> rows g,g+8; cols 2tg,2tg+1
    int colg = bx * 128 + wn * 32;
    int rowg = by * BM + wm * (BM / 2);
    #pragma unroll
    for (int mt = 0; mt < MT; mt++) {
        #pragma unroll
        for (int half = 0; half < 2; half++) {
            int row = rowg + mt * 16 + g + half * 8;
            #pragma unroll
            for (int j = 0; j < 4; j++) {
                int col = colg + j * 8 + tg * 2;
                float v0 = c[mt][j][half * 2 + 0];
                float v1 = c[mt][j][half * 2 + 1];
                if (epi >= 1) { v0 += bias[col]; v1 += bias[col + 1]; }
                if (epi == 2) { v0 = gelu_exact(v0); v1 = gelu_exact(v1); }
                if constexpr (sizeof(OutT) == 4) {
                    float2 w; w.x = v0; w.y = v1;
                    *reinterpret_cast<float2*>((float*)C + (size_t)row * N + col) = w;
                } else {
                    *reinterpret_cast<__half2*>((__half*)C + (size_t)row * N + col) =
                        __floats2half2_rn(v0, v1);
                }
            }
        }
    }
}

template<int BM, typename OutT>
__global__ __launch_bounds__(256, 2)
void gemm_f16(const __half* __restrict__ A, const __half* __restrict__ B,
              const float* __restrict__ bias, OutT* __restrict__ C,
              int N, int K, int epi)
{
    extern __shared__ __half smh[];
    gemm_body<BM, OutT>(A, B, bias, C, N, K, epi, blockIdx.x, blockIdx.y, smh);
}

// ---------------- streaming causal attention (no-max custom softmax) --------
// reads packed qkv fp32 [M][2304]; writes fp16 av
#define ATTN_SMEM ((3 * 64 * 65 + 64) * 4)

__global__ void attn_kernel(const float* __restrict__ qkv, __half* __restrict__ o) {
    extern __shared__ float sm[];
    float* qs    = sm;
    float* es    = sm + 64 * 65;
    float* vs    = sm + 2 * 64 * 65;
    float* denom = sm + 3 * 64 * 65;

    int qt = blockIdx.x;
    int bh = blockIdx.y;
    int b = bh / HH, hh = bh % HH;
    const float* qb = qkv + (size_t)b * SS * NQKV + hh * DKK;
    const float* kb = qb + DD;
    const float* vb = qb + 2 * DD;

    int tid = threadIdx.x;
    int tx = tid & 15, ty = tid >> 4;

    for (int idx = tid; idx < 64 * 64; idx += 256) {
        int r = idx >> 6, c = idx & 63;
        qs[r * 65 + c] = qb[(size_t)(qt * 64 + r) * NQKV + c];
    }
    if (tid < 64) denom[tid] = 0.f;
    float oacc[4][4];
    #pragma unroll
    for (int i = 0; i < 4; i++)
        #pragma unroll
        for (int j = 0; j < 4; j++) oacc[i][j] = 0.f;
    __syncthreads();

    for (int kt = 0; kt <= qt; kt++) {
        for (int idx = tid; idx < 64 * 64; idx += 256) {
            int r = idx >> 6, c = idx & 63;
            es[r * 65 + c] = kb[(size_t)(kt * 64 + r) * NQKV + c];
            vs[r * 65 + c] = vb[(size_t)(kt * 64 + r) * NQKV + c];
        }
        __syncthreads();

        float s[4][4];
        #pragma unroll
        for (int i = 0; i < 4; i++)
            #pragma unroll
            for (int j = 0; j < 4; j++) s[i][j] = 0.f;
        #pragma unroll 8
        for (int d = 0; d < 64; d++) {
            float aq[4], ak[4];
            #pragma unroll
            for (int i = 0; i < 4; i++) aq[i] = qs[(ty * 4 + i) * 65 + d];
            #pragma unroll
            for (int j = 0; j < 4; j++) ak[j] = es[(tx * 4 + j) * 65 + d];
            #pragma unroll
            for (int i = 0; i < 4; i++)
                #pragma unroll
                for (int j = 0; j < 4; j++) s[i][j] += aq[i] * ak[j];
        }
        __syncthreads();

        #pragma unroll
        for (int i = 0; i < 4; i++) {
            int qg = qt * 64 + ty * 4 + i;
            float rs = 0.f;
            #pragma unroll
            for (int j = 0; j < 4; j++) {
                int kg = kt * 64 + tx * 4 + j;
                float e = (kg < qg) ? expf(s[i][j] * 0.125f) : 0.f;
                es[(ty * 4 + i) * 65 + (tx * 4 + j)] = e;
                rs += e;
            }
            atomicAdd(&denom[ty * 4 + i], rs);
        }
        __syncthreads();

        #pragma unroll 4
        for (int kk = 0; kk < 64; kk++) {
            float ef[4], vf[4];
            #pragma unroll
            for (int i = 0; i < 4; i++) ef[i] = es[(ty * 4 + i) * 65 + kk];
            #pragma unroll
            for (int j = 0; j < 4; j++) vf[j] = vs[kk * 65 + tx * 4 + j];
            #pragma unroll
            for (int i = 0; i < 4; i++)
                #pragma unroll
                for (int j = 0; j < 4; j++) oacc[i][j] += ef[i] * vf[j];
        }
        __syncthreads();
    }

    #pragma unroll
    for (int i = 0; i < 4; i++) {
        int qg = qt * 64 + ty * 4 + i;
        float dn = denom[ty * 4 + i] + 1e-9f;
        size_t base = (size_t)(b * SS + qg) * DD + hh * DKK + tx * 4;
        *reinterpret_cast<__half2*>(o + base) =
            __floats2half2_rn(oacc[i][0] / dn, oacc[i][1] / dn);
        *reinterpret_cast<__half2*>(o + base + 2) =
            __floats2half2_rn(oacc[i][2] / dn, oacc[i][3] / dn);
    }
}

// ---------------- fused residual-add + LayerNorm (writes fp32 + fp16) --------
__device__ __forceinline__ float block_reduce_sum(float v, float* sh) {
    int tid = threadIdx.x;
    #pragma unroll
    for (int o = 16; o; o >>= 1) v += __shfl_xor_sync(0xffffffffu, v, o);
    if ((tid & 31) == 0) sh[tid >> 5] = v;
    __syncthreads();
    float r = 0.f;
    if (tid < 8) r = sh[tid];
    if (tid < 32) {
        #pragma unroll
        for (int o = 4; o; o >>= 1) r += __shfl_xor_sync(0xffffffffu, r, o);
    }
    if (tid == 0) sh[0] = r;
    __syncthreads();
    float out = sh[0];
    __syncthreads();
    return out;
}

__global__ void ln_kernel(float* __restrict__ h, const float* __restrict__ delta,
                          const float* __restrict__ gs, const float* __restrict__ gb,
                          __half* __restrict__ h16) {
    __shared__ float sh[8];
    int row = blockIdx.x, tid = threadIdx.x;
    size_t base = (size_t)row * DD;
    float v[3];
    float sum = 0.f;
    #pragma unroll
    for (int t = 0; t < 3; t++) {
        int c = tid + t * 256;
        v[t] = h[base + c] + delta[base + c];
        sum += v[t];
    }
    float mean = block_reduce_sum(sum, sh) * (1.0f / 768.0f);
    float sq = 0.f;
    #pragma unroll
    for (int t = 0; t < 3; t++) { float d = v[t] - mean; sq += d * d; }
    float var = block_reduce_sum(sq, sh) * (1.0f / 768.0f);
    float inv = rsqrtf(var + 1e-5f);
    #pragma unroll
    for (int t = 0; t < 3; t++) {
        int c = tid + t * 256;
        float r = (v[t] - mean) * inv * gs[c] + gb[c];
        h[base + c] = r;
        h16[base + c] = __float2half(r);
    }
}

// ---------------- launcher ---------------------------------------------------
extern "C" void kernel_launch(void* const* d_in, const int* in_sizes, int n_in,
                              void* d_out, int out_size) {
    const int*   x     = (const int*)  d_in[0];
    const float* emb   = (const float*)d_in[1];
    const float* Wq    = (const float*)d_in[2];
    const float* Wk    = (const float*)d_in[3];
    const float* Wv    = (const float*)d_in[4];
    const float* Wo    = (const float*)d_in[5];
    const float* ln1_s = (const float*)d_in[6];
    const float* ln1_b = (const float*)d_in[7];
    const float* W1    = (const float*)d_in[8];
    const float* b1    = (const float*)d_in[9];
    const float* W2    = (const float*)d_in[10];
    const float* b2    = (const float*)d_in[11];
    const float* ln2_s = (const float*)d_in[12];
    const float* ln2_b = (const float*)d_in[13];
    const float* lm_W  = (const float*)d_in[14];
    const float* lm_b  = (const float*)d_in[15];
    float* out = (float*)d_out;

    float *h_, *qkv_, *tmp_;
    __half *h16_, *av16_, *ff16_, *wqkv16_, *wo16_, *w116_, *w216_, *lm16_;
    cudaGetSymbolAddress((void**)&h_,    g_h);
    cudaGetSymbolAddress((void**)&qkv_,  g_qkv);
    cudaGetSymbolAddress((void**)&tmp_,  g_tmp);
    cudaGetSymbolAddress((void**)&h16_,  g_h16);
    cudaGetSymbolAddress((void**)&av16_, g_av16);
    cudaGetSymbolAddress((void**)&ff16_, g_ff16);
    cudaGetSymbolAddress((void**)&wqkv16_, g_wqkv16);
    cudaGetSymbolAddress((void**)&wo16_,   g_wo16);
    cudaGetSymbolAddress((void**)&w116_,   g_w116);
    cudaGetSymbolAddress((void**)&w216_,   g_w216);
    cudaGetSymbolAddress((void**)&lm16_,   g_lm16);

    const int SM128 = SMEM_GEMM_BYTES(128);
    const int SM64  = SMEM_GEMM_BYTES(64);
    cudaFuncSetAttribute(attn_kernel, cudaFuncAttributeMaxDynamicSharedMemorySize, ATTN_SMEM);
    cudaFuncSetAttribute((const void*)gemm_f16<128, float>,  cudaFuncAttributeMaxDynamicSharedMemorySize, SM128);
    cudaFuncSetAttribute((const void*)gemm_f16<128, __half>, cudaFuncAttributeMaxDynamicSharedMemorySize, SM128);
    cudaFuncSetAttribute((const void*)gemm_f16<64, float>,   cudaFuncAttributeMaxDynamicSharedMemorySize, SM64);

    // ---- weight conversion (every launch; deterministic) ----
    {
        int n4;
        n4 = LL * DD * NQKV / 4;
        qkv_pack<<<(n4 + 255) / 256, 256>>>(Wq, Wk, Wv, (__half2*)wqkv16_, n4);
        n4 = LL * DD * DD / 4;
        f32_to_f16<<<(n4 + 255) / 256, 256>>>(Wo, (__half2*)wo16_, n4);
        n4 = LL * DD * DFFF / 4;
        f32_to_f16<<<(n4 + 255) / 256, 256>>>(W1, (__half2*)w116_, n4);
        f32_to_f16<<<(n4 + 255) / 256, 256>>>(W2, (__half2*)w216_, n4);
        n4 = DD * VV / 4;
        f32_to_f16<<<(n4 + 255) / 256, 256>>>(lm_W, (__half2*)lm16_, n4);
    }

    embed_kernel<<<MM, 256>>>(x, emb, h_, h16_);

    dim3 gQKV(NQKV / 128, MM / 128);    // (18,16)
    dim3 gN768(DD / 128, MM / 64);      // (6,32)  BM=64
    dim3 gFF1(DFFF / 128, MM / 128);    // (24,16)
    dim3 gLM(VV / 128, MM / 128);       // (250,16)
    dim3 gAttn(SS / 64, BB * HH);       // (16,24)

    for (int l = 0; l < LL; l++) {
        const __half* wqkv_l = wqkv16_ + (size_t)l * DD * NQKV;
        const __half* wo_l   = wo16_   + (size_t)l * DD * DD;
        const __half* w1_l   = w116_   + (size_t)l * DD * DFFF;
        const __half* w2_l   = w216_   + (size_t)l * DFFF * DD;

        gemm_f16<128, float><<<gQKV, 256, SM128>>>(h16_, wqkv_l, nullptr, qkv_, NQKV, DD, 0);

        attn_kernel<<<gAttn, 256, ATTN_SMEM>>>(qkv_, av16_);

        gemm_f16<64, float><<<gN768, 256, SM64>>>(av16_, wo_l, nullptr, tmp_, DD, DD, 0);
        ln_kernel<<<MM, 256>>>(h_, tmp_, ln1_s + (size_t)l * DD, ln1_b + (size_t)l * DD, h16_);

        gemm_f16<128, __half><<<gFF1, 256, SM128>>>(h16_, w1_l, b1 + (size_t)l * DFFF, ff16_, DFFF, DD, 2);
        gemm_f16<64, float><<<gN768, 256, SM64>>>(ff16_, w2_l, b2 + (size_t)l * DD, tmp_, DD, DFFF, 1);
        ln_kernel<<<MM, 256>>>(h_, tmp_, ln2_s + (size_t)l * DD, ln2_b + (size_t)l * DD, h16_);
    }

    gemm_f16<128, float><<<gLM, 256, SM128>>>(h16_, lm16_, lm_b, out, VV, DD, 1);
}

// round 5
// speedup vs baseline: 5.5444x; 1.6540x over previous
#include <cuda_runtime.h>
#include <cuda_fp16.h>
#include <math.h>

// Problem constants
#define BB 2
#define SS 1024
#define DD 768
#define HH 12
#define DKK 64
#define DFFF 3072
#define VV 32000
#define LL 4
#define MM (BB*SS)       // 2048
#define NQKV (3*DD)      // 2304

// ---------------- scratch (static device globals; no allocation) -------------
__device__ float  g_h    [MM*DD];
__device__ float  g_tmp  [MM*DD];
__device__ __half g_h16  [MM*DD];
__device__ __half g_qkv16[MM*NQKV];
__device__ __half g_av16 [MM*DD];
__device__ __half g_ff16 [MM*DFFF];
// fp16 weights
__device__ __half g_wqkv16[LL*DD*NQKV];   // packed [l][k][which*768+n]
__device__ __half g_wo16  [LL*DD*DD];
__device__ __half g_w116  [LL*DD*DFFF];
__device__ __half g_w216  [LL*DFFF*DD];
__device__ __half g_lm16  [DD*VV];

// ---------------- fp32 -> fp16 conversion ------------------------------------
__global__ void f32_to_f16(const float* __restrict__ src, __half2* __restrict__ dst, int n4) {
    int i = blockIdx.x * blockDim.x + threadIdx.x;
    if (i < n4) {
        float4 v = reinterpret_cast<const float4*>(src)[i];
        dst[2 * i + 0] = __floats2half2_rn(v.x, v.y);
        dst[2 * i + 1] = __floats2half2_rn(v.z, v.w);
    }
}

// pack Wq/Wk/Wv (each [L][768][768]) into [L][768][2304] fp16
__global__ void qkv_pack(const float* __restrict__ Wq, const float* __restrict__ Wk,
                         const float* __restrict__ Wv, __half2* __restrict__ dst, int n4) {
    int i = blockIdx.x * blockDim.x + threadIdx.x;
    if (i >= n4) return;
    int e = i * 4;
    int c = e % NQKV;
    int k = (e / NQKV) % DD;
    int l = e / (NQKV * DD);
    int which = c / DD;
    int n = c % DD;
    const float* W = (which == 0) ? Wq : (which == 1) ? Wk : Wv;
    float4 v = *reinterpret_cast<const float4*>(W + (size_t)l * DD * DD + (size_t)k * DD + n);
    dst[2 * i + 0] = __floats2half2_rn(v.x, v.y);
    dst[2 * i + 1] = __floats2half2_rn(v.z, v.w);
}

// ---------------- embedding + sinusoidal PE ----------------------------------
__global__ void embed_kernel(const int* __restrict__ x, const float* __restrict__ emb,
                             float* __restrict__ h, __half* __restrict__ h16) {
    int row = blockIdx.x;
    int s = row & (SS - 1);
    int tok = x[row];
    for (int c = threadIdx.x; c < DD; c += blockDim.x) {
        float ef = (float)(c & ~1) / (float)DD;
        float sc = powf(10000.0f, ef);
        float ang = (float)s / sc;
        float pe = (c & 1) ? cosf(ang) : sinf(ang);
        float v = emb[(size_t)tok * DD + c] + pe;
        h[(size_t)row * DD + c] = v;
        h16[(size_t)row * DD + c] = __float2half(v);
    }
}

// ---------------- common PTX helpers -----------------------------------------
__device__ __forceinline__ float gelu_exact(float x) {
    return 0.5f * x * (1.0f + erff(x * 0.7071067811865476f));
}

#define CPA16(dst, src) asm volatile("cp.async.cg.shared.global [%0], [%1], 16;" :: "r"(dst), "l"(src))
#define LDSM4(r0,r1,r2,r3,addr) \
    asm volatile("ldmatrix.sync.aligned.m8n8.x4.shared.b16 {%0,%1,%2,%3},[%4];" \
                 : "=r"(r0),"=r"(r1),"=r"(r2),"=r"(r3) : "r"(addr))
#define LDSM4T(r0,r1,r2,r3,addr) \
    asm volatile("ldmatrix.sync.aligned.m8n8.x4.trans.shared.b16 {%0,%1,%2,%3},[%4];" \
                 : "=r"(r0),"=r"(r1),"=r"(r2),"=r"(r3) : "r"(addr))

__device__ __forceinline__ void mma16816(float c[4], const unsigned a[4], const unsigned b[2]) {
    asm volatile("mma.sync.aligned.m16n8k16.row.col.f32.f16.f16.f32 "
                 "{%0,%1,%2,%3},{%4,%5,%6,%7},{%8,%9},{%0,%1,%2,%3};"
                 : "+f"(c[0]), "+f"(c[1]), "+f"(c[2]), "+f"(c[3])
                 : "r"(a[0]), "r"(a[1]), "r"(a[2]), "r"(a[3]), "r"(b[0]), "r"(b[1]));
}

__device__ __forceinline__ unsigned cvta_s(const void* p) {
    return (unsigned)__cvta_generic_to_shared(p);
}
__device__ __forceinline__ unsigned packh2(float x, float y) {
    __half2 h = __floats2half2_rn(x, y);
    return *reinterpret_cast<unsigned*>(&h);
}

// ---------------- fp16 tensor-core GEMM (ldmatrix + m16n8k16) ----------------
#define ASTR 40
#define BSTR 136
#define BBUF_H (32*BSTR)
#define SMEM_GEMM_BYTES(BM) ((2*(BM)*ASTR + 2*BBUF_H) * 2)

template<int BM, typename OutT>
__device__ __forceinline__ void gemm_body(
    const __half* __restrict__ A, const __half* __restrict__ B,
    const float* __restrict__ bias, OutT* __restrict__ C,
    int N, int K, int epi, int bx, int by, __half* sm)
{
    constexpr int MT = BM / 32;
    constexpr int ABUF_H = BM * ASTR;

    __half* As = sm;
    __half* Bs = sm + 2 * ABUF_H;

    int tid = threadIdx.x;
    int lane = tid & 31;
    int warp = tid >> 5;
    int wm = warp >> 2;
    int wn = warp & 3;
    int g  = lane >> 2;
    int tg = lane & 3;

    const __half* Ab = A + (size_t)by * BM * K;
    const __half* Bb = B + (size_t)bx * 128;

    float c[MT][4][4];
    #pragma unroll
    for (int i = 0; i < MT; i++)
        #pragma unroll
        for (int j = 0; j < 4; j++)
            #pragma unroll
            for (int r = 0; r < 4; r++) c[i][j][r] = 0.f;

    const int T = K >> 5;

    auto load_tile = [&](int kt, int buf) {
        __half* Ad = As + buf * ABUF_H;
        __half* Bd = Bs + buf * BBUF_H;
        #pragma unroll
        for (int i = 0; i < BM / 64; i++) {
            int s = tid + i * 256;
            int r  = s >> 2;
            int k8 = (s & 3) * 8;
            unsigned dst = cvta_s(Ad + r * ASTR + k8);
            CPA16(dst, Ab + (size_t)r * K + kt + k8);
        }
        #pragma unroll
        for (int i = 0; i < 2; i++) {
            int s = tid + i * 256;
            int r  = s >> 4;
            int n8 = (s & 15) * 8;
            unsigned dst = cvta_s(Bd + r * BSTR + n8);
            CPA16(dst, Bb + (size_t)(kt + r) * N + n8);
        }
    };

    load_tile(0, 0);
    asm volatile("cp.async.commit_group;");

    unsigned aBase = cvta_s(As + (wm * (BM / 2) + (lane & 15)) * ASTR + (lane >> 4) * 8);
    unsigned bBase = cvta_s(Bs + (lane & 15) * BSTR + wn * 32 + (lane >> 4) * 8);

    for (int t = 0; t < T; t++) {
        asm volatile("cp.async.wait_group 0;");
        __syncthreads();
        if (t + 1 < T) {
            load_tile((t + 1) * 32, (t + 1) & 1);
            asm volatile("cp.async.commit_group;");
        }

        unsigned aB = aBase + (t & 1) * (ABUF_H * 2);
        unsigned bB = bBase + (t & 1) * (BBUF_H * 2);

        #pragma unroll
        for (int kb = 0; kb < 2; kb++) {
            unsigned a[MT][4], b[4][2];
            #pragma unroll
            for (int mt = 0; mt < MT; mt++) {
                LDSM4(a[mt][0], a[mt][1], a[mt][2], a[mt][3],
                      aB + (mt * 16 * ASTR + kb * 16) * 2);
            }
            #pragma unroll
            for (int nb = 0; nb < 2; nb++) {
                unsigned t0, t1, t2, t3;
                LDSM4T(t0, t1, t2, t3, bB + (kb * 16 * BSTR + nb * 16) * 2);
                b[2 * nb][0] = t0; b[2 * nb][1] = t1;
                b[2 * nb + 1][0] = t2; b[2 * nb + 1][1] = t3;
            }
            #pragma unroll
            for (int mt = 0; mt < MT; mt++)
                #pragma unroll
                for (int j = 0; j < 4; j++)
                    mma16816(c[mt][j], a[mt], b[j]);
        }
        __syncthreads();
    }

    int colg = bx * 128 + wn * 32;
    int rowg = by * BM + wm * (BM / 2);
    #pragma unroll
    for (int mt = 0; mt < MT; mt++) {
        #pragma unroll
        for (int half = 0; half < 2; half++) {
            int row = rowg + mt * 16 + g + half * 8;
            #pragma unroll
            for (int j = 0; j < 4; j++) {
                int col = colg + j * 8 + tg * 2;
                float v0 = c[mt][j][half * 2 + 0];
                float v1 = c[mt][j][half * 2 + 1];
                if (epi >= 1) { v0 += bias[col]; v1 += bias[col + 1]; }
                if (epi == 2) { v0 = gelu_exact(v0); v1 = gelu_exact(v1); }
                if constexpr (sizeof(OutT) == 4) {
                    float2 w; w.x = v0; w.y = v1;
                    *reinterpret_cast<float2*>((float*)C + (size_t)row * N + col) = w;
                } else {
                    *reinterpret_cast<__half2*>((__half*)C + (size_t)row * N + col) =
                        __floats2half2_rn(v0, v1);
                }
            }
        }
    }
}

template<int BM, typename OutT>
__global__ __launch_bounds__(256, 2)
void gemm_f16(const __half* __restrict__ A, const __half* __restrict__ B,
              const float* __restrict__ bias, OutT* __restrict__ C,
              int N, int K, int epi)
{
    extern __shared__ __half smh[];
    gemm_body<BM, OutT>(A, B, bias, C, N, K, epi, blockIdx.x, blockIdx.y, smh);
}

// ---------------- fp16 tensor-core causal attention --------------------------
// reads packed qkv fp16 [M][2304]; writes fp16 av [M][768]
// custom no-max softmax: e=exp(s/8) masked kg<qg; out = e@V / (sum e + 1e-9)
#define QSTR 72                 // halves per smem row (144B; ldmatrix conflict-free)
#define KVBUF (64*QSTR)
#define ATTN_SMEM_BYTES (5 * KVBUF * 2)   // Q + 2xK + 2xV = 46080 B

__global__ __launch_bounds__(128, 4)
void attn_f16(const __half* __restrict__ qkv, __half* __restrict__ o) {
    extern __shared__ __half smh[];
    __half* Qs = smh;
    __half* Ks = smh + KVBUF;        // [2][64][QSTR]
    __half* Vs = smh + 3 * KVBUF;    // [2][64][QSTR]

    int qt = blockIdx.x;
    int bh = blockIdx.y;
    int b = bh / HH, hh = bh % HH;
    const __half* qb = qkv + (size_t)b * SS * NQKV + hh * DKK;
    const __half* kb = qb + DD;
    const __half* vb = qb + 2 * DD;

    int tid = threadIdx.x;
    int lane = tid & 31;
    int warp = tid >> 5;
    int g  = lane >> 2;
    int tg = lane & 3;

    // load Q tile (64 rows x 64 halves = 512 16B segs / 128 thr = 4 each)
    #pragma unroll
    for (int i = 0; i < 4; i++) {
        int s = tid + i * 128;
        int r = s >> 3;
        int c8 = (s & 7) * 8;
        CPA16(cvta_s(Qs + r * QSTR + c8), qb + (size_t)(qt * 64 + r) * NQKV + c8);
    }
    auto load_kv = [&](int kt, int buf) {
        __half* Kd = Ks + buf * KVBUF;
        __half* Vd = Vs + buf * KVBUF;
        #pragma unroll
        for (int i = 0; i < 4; i++) {
            int s = tid + i * 128;
            int r = s >> 3;
            int c8 = (s & 7) * 8;
            CPA16(cvta_s(Kd + r * QSTR + c8), kb + (size_t)(kt * 64 + r) * NQKV + c8);
            CPA16(cvta_s(Vd + r * QSTR + c8), vb + (size_t)(kt * 64 + r) * NQKV + c8);
        }
    };
    load_kv(0, 0);
    asm volatile("cp.async.commit_group;");

    float oacc[8][4];
    #pragma unroll
    for (int i = 0; i < 8; i++)
        #pragma unroll
        for (int j = 0; j < 4; j++) oacc[i][j] = 0.f;
    float den0 = 0.f, den1 = 0.f;

    unsigned qAddr = cvta_s(Qs + (warp * 16 + (lane & 15)) * QSTR + (lane >> 4) * 8);
    int qg0 = qt * 64 + warp * 16 + g;   // thread's first q row (second = +8)

    for (int kt = 0; kt <= qt; kt++) {
        asm volatile("cp.async.wait_group 0;");
        __syncthreads();
        if (kt < qt) {
            load_kv(kt + 1, (kt + 1) & 1);
            asm volatile("cp.async.commit_group;");
        }
        const __half* Kb_ = Ks + (kt & 1) * KVBUF;
        const __half* Vb_ = Vs + (kt & 1) * KVBUF;

        // S = Q K^T  (16 q-rows x 64 kv per warp)
        float s[8][4];
        #pragma unroll
        for (int i = 0; i < 8; i++)
            #pragma unroll
            for (int j = 0; j < 4; j++) s[i][j] = 0.f;

        #pragma unroll
        for (int kbk = 0; kbk < 4; kbk++) {
            unsigned a[4];
            LDSM4(a[0], a[1], a[2], a[3], qAddr + kbk * 16 * 2);
            #pragma unroll
            for (int nb2 = 0; nb2 < 4; nb2++) {
                unsigned r0, r1, r2, r3;
                LDSM4(r0, r1, r2, r3,
                      cvta_s(Kb_ + (nb2 * 16 + (lane & 15)) * QSTR + kbk * 16 + (lane >> 4) * 8));
                unsigned b0[2] = { r0, r2 };
                unsigned b1[2] = { r1, r3 };
                mma16816(s[2 * nb2],     a, b0);
                mma16816(s[2 * nb2 + 1], a, b1);
            }
        }

        // mask (strict causal: kg < qg) + exp, accumulate row denominators
        bool diag = (kt == qt);
        #pragma unroll
        for (int nb = 0; nb < 8; nb++) {
            int kg = kt * 64 + nb * 8 + 2 * tg;
            float e0 = (!diag || kg     < qg0)     ? expf(s[nb][0] * 0.125f) : 0.f;
            float e1 = (!diag || kg + 1 < qg0)     ? expf(s[nb][1] * 0.125f) : 0.f;
            float e2 = (!diag || kg     < qg0 + 8) ? expf(s[nb][2] * 0.125f) : 0.f;
            float e3 = (!diag || kg + 1 < qg0 + 8) ? expf(s[nb][3] * 0.125f) : 0.f;
            s[nb][0] = e0; s[nb][1] = e1; s[nb][2] = e2; s[nb][3] = e3;
            den0 += e0 + e1;
            den1 += e2 + e3;
        }

        // O += P @ V   (P A-fragments repacked from S accumulators)
        #pragma unroll
        for (int kbk = 0; kbk < 4; kbk++) {
            unsigned a[4];
            a[0] = packh2(s[2 * kbk][0],     s[2 * kbk][1]);
            a[1] = packh2(s[2 * kbk][2],     s[2 * kbk][3]);
            a[2] = packh2(s[2 * kbk + 1][0], s[2 * kbk + 1][1]);
            a[3] = packh2(s[2 * kbk + 1][2], s[2 * kbk + 1][3]);
            #pragma unroll
            for (int nb2 = 0; nb2 < 4; nb2++) {
                unsigned t0, t1, t2, t3;
                LDSM4T(t0, t1, t2, t3,
                       cvta_s(Vb_ + (kbk * 16 + (lane & 15)) * QSTR + nb2 * 16 + (lane >> 4) * 8));
                unsigned b0[2] = { t0, t1 };
                unsigned b1[2] = { t2, t3 };
                mma16816(oacc[2 * nb2],     a, b0);
                mma16816(oacc[2 * nb2 + 1], a, b1);
            }
        }
    }

    // quad-reduce denominators (lanes g*4+tg share q rows)
    den0 += __shfl_xor_sync(0xffffffffu, den0, 1);
    den0 += __shfl_xor_sync(0xffffffffu, den0, 2);
    den1 += __shfl_xor_sync(0xffffffffu, den1, 1);
    den1 += __shfl_xor_sync(0xffffffffu, den1, 2);
    float inv0 = 1.0f / (den0 + 1e-9f);
    float inv1 = 1.0f / (den1 + 1e-9f);

    int row0 = b * SS + qg0;
    #pragma unroll
    for (int nb = 0; nb < 8; nb++) {
        int col = hh * DKK + nb * 8 + 2 * tg;
        *reinterpret_cast<__half2*>(o + (size_t)row0 * DD + col) =
            __floats2half2_rn(oacc[nb][0] * inv0, oacc[nb][1] * inv0);
        *reinterpret_cast<__half2*>(o + (size_t)(row0 + 8) * DD + col) =
            __floats2half2_rn(oacc[nb][2] * inv1, oacc[nb][3] * inv1);
    }
}

// ---------------- fused residual-add + LayerNorm (writes fp32 + fp16) --------
__device__ __forceinline__ float block_reduce_sum(float v, float* sh) {
    int tid = threadIdx.x;
    #pragma unroll
    for (int o = 16; o; o >>= 1) v += __shfl_xor_sync(0xffffffffu, v, o);
    if ((tid & 31) == 0) sh[tid >> 5] = v;
    __syncthreads();
    float r = 0.f;
    if (tid < 8) r = sh[tid];
    if (tid < 32) {
        #pragma unroll
        for (int o = 4; o; o >>= 1) r += __shfl_xor_sync(0xffffffffu, r, o);
    }
    if (tid == 0) sh[0] = r;
    __syncthreads();
    float out = sh[0];
    __syncthreads();
    return out;
}

__global__ void ln_kernel(float* __restrict__ h, const float* __restrict__ delta,
                          const float* __restrict__ gs, const float* __restrict__ gb,
                          __half* __restrict__ h16) {
    __shared__ float sh[8];
    int row = blockIdx.x, tid = threadIdx.x;
    size_t base = (size_t)row * DD;
    float v[3];
    float sum = 0.f;
    #pragma unroll
    for (int t = 0; t < 3; t++) {
        int c = tid + t * 256;
        v[t] = h[base + c] + delta[base + c];
        sum += v[t];
    }
    float mean = block_reduce_sum(sum, sh) * (1.0f / 768.0f);
    float sq = 0.f;
    #pragma unroll
    for (int t = 0; t < 3; t++) { float d = v[t] - mean; sq += d * d; }
    float var = block_reduce_sum(sq, sh) * (1.0f / 768.0f);
    float inv = rsqrtf(var + 1e-5f);
    #pragma unroll
    for (int t = 0; t < 3; t++) {
        int c = tid + t * 256;
        float r = (v[t] - mean) * inv * gs[c] + gb[c];
        h[base + c] = r;
        h16[base + c] = __float2half(r);
    }
}

// ---------------- launcher ---------------------------------------------------
extern "C" void kernel_launch(void* const* d_in, const int* in_sizes, int n_in,
                              void* d_out, int out_size) {
    const int*   x     = (const int*)  d_in[0];
    const float* emb   = (const float*)d_in[1];
    const float* Wq    = (const float*)d_in[2];
    const float* Wk    = (const float*)d_in[3];
    const float* Wv    = (const float*)d_in[4];
    const float* Wo    = (const float*)d_in[5];
    const float* ln1_s = (const float*)d_in[6];
    const float* ln1_b = (const float*)d_in[7];
    const float* W1    = (const float*)d_in[8];
    const float* b1    = (const float*)d_in[9];
    const float* W2    = (const float*)d_in[10];
    const float* b2    = (const float*)d_in[11];
    const float* ln2_s = (const float*)d_in[12];
    const float* ln2_b = (const float*)d_in[13];
    const float* lm_W  = (const float*)d_in[14];
    const float* lm_b  = (const float*)d_in[15];
    float* out = (float*)d_out;

    float *h_, *tmp_;
    __half *h16_, *qkv16_, *av16_, *ff16_, *wqkv16_, *wo16_, *w116_, *w216_, *lm16_;
    cudaGetSymbolAddress((void**)&h_,     g_h);
    cudaGetSymbolAddress((void**)&tmp_,   g_tmp);
    cudaGetSymbolAddress((void**)&h16_,   g_h16);
    cudaGetSymbolAddress((void**)&qkv16_, g_qkv16);
    cudaGetSymbolAddress((void**)&av16_,  g_av16);
    cudaGetSymbolAddress((void**)&ff16_,  g_ff16);
    cudaGetSymbolAddress((void**)&wqkv16_, g_wqkv16);
    cudaGetSymbolAddress((void**)&wo16_,   g_wo16);
    cudaGetSymbolAddress((void**)&w116_,   g_w116);
    cudaGetSymbolAddress((void**)&w216_,   g_w216);
    cudaGetSymbolAddress((void**)&lm16_,   g_lm16);

    const int SM128 = SMEM_GEMM_BYTES(128);
    const int SM64  = SMEM_GEMM_BYTES(64);
    cudaFuncSetAttribute(attn_f16, cudaFuncAttributeMaxDynamicSharedMemorySize, ATTN_SMEM_BYTES);
    cudaFuncSetAttribute((const void*)gemm_f16<128, float>,  cudaFuncAttributeMaxDynamicSharedMemorySize, SM128);
    cudaFuncSetAttribute((const void*)gemm_f16<128, __half>, cudaFuncAttributeMaxDynamicSharedMemorySize, SM128);
    cudaFuncSetAttribute((const void*)gemm_f16<64, float>,   cudaFuncAttributeMaxDynamicSharedMemorySize, SM64);

    // ---- weight conversion (every launch; deterministic) ----
    {
        int n4;
        n4 = LL * DD * NQKV / 4;
        qkv_pack<<<(n4 + 255) / 256, 256>>>(Wq, Wk, Wv, (__half2*)wqkv16_, n4);
        n4 = LL * DD * DD / 4;
        f32_to_f16<<<(n4 + 255) / 256, 256>>>(Wo, (__half2*)wo16_, n4);
        n4 = LL * DD * DFFF / 4;
        f32_to_f16<<<(n4 + 255) / 256, 256>>>(W1, (__half2*)w116_, n4);
        f32_to_f16<<<(n4 + 255) / 256, 256>>>(W2, (__half2*)w216_, n4);
        n4 = DD * VV / 4;
        f32_to_f16<<<(n4 + 255) / 256, 256>>>(lm_W, (__half2*)lm16_, n4);
    }

    embed_kernel<<<MM, 256>>>(x, emb, h_, h16_);

    dim3 gQKV(NQKV / 128, MM / 128);    // (18,16)
    dim3 gN768(DD / 128, MM / 64);      // (6,32)  BM=64
    dim3 gFF1(DFFF / 128, MM / 128);    // (24,16)
    dim3 gLM(VV / 128, MM / 128);       // (250,16)
    dim3 gAttn(SS / 64, BB * HH);       // (16,24)

    for (int l = 0; l < LL; l++) {
        const __half* wqkv_l = wqkv16_ + (size_t)l * DD * NQKV;
        const __half* wo_l   = wo16_   + (size_t)l * DD * DD;
        const __half* w1_l   = w116_   + (size_t)l * DD * DFFF;
        const __half* w2_l   = w216_   + (size_t)l * DFFF * DD;

        gemm_f16<128, __half><<<gQKV, 256, SM128>>>(h16_, wqkv_l, nullptr, qkv16_, NQKV, DD, 0);

        attn_f16<<<gAttn, 128, ATTN_SMEM_BYTES>>>(qkv16_, av16_);

        gemm_f16<64, float><<<gN768, 256, SM64>>>(av16_, wo_l, nullptr, tmp_, DD, DD, 0);
        ln_kernel<<<MM, 256>>>(h_, tmp_, ln1_s + (size_t)l * DD, ln1_b + (size_t)l * DD, h16_);

        gemm_f16<128, __half><<<gFF1, 256, SM128>>>(h16_, w1_l, b1 + (size_t)l * DFFF, ff16_, DFFF, DD, 2);
        gemm_f16<64, float><<<gN768, 256, SM64>>>(ff16_, w2_l, b2 + (size_t)l * DD, tmp_, DD, DFFF, 1);
        ln_kernel<<<MM, 256>>>(h_, tmp_, ln2_s + (size_t)l * DD, ln2_b + (size_t)l * DD, h16_);
    }

    gemm_f16<128, float><<<gLM, 256, SM128>>>(h16_, lm16_, lm_b, out, VV, DD, 1);
}

// round 7
// speedup vs baseline: 6.1342x; 1.1064x over previous
#include <cuda_runtime.h>
#include <cuda_fp16.h>
#include <math.h>

// Problem constants
#define BB 2
#define SS 1024
#define DD 768
#define HH 12
#define DKK 64
#define DFFF 3072
#define VV 32000
#define LL 4
#define MM (BB*SS)       // 2048
#define NQKV (3*DD)      // 2304

// ---------------- scratch (static device globals; no allocation) -------------
__device__ float  g_h    [MM*DD];
__device__ float  g_tmp  [MM*DD];
__device__ __half g_h16  [MM*DD];
__device__ __half g_qkv16[MM*NQKV];
__device__ __half g_av16 [MM*DD];
__device__ __half g_ff16 [MM*DFFF];
// fp16 weights
__device__ __half g_wqkv16[LL*DD*NQKV];   // packed [l][k][which*768+n]
__device__ __half g_wo16  [LL*DD*DD];
__device__ __half g_w116  [LL*DD*DFFF];
__device__ __half g_w216  [LL*DFFF*DD];
__device__ __half g_lm16  [DD*VV];

// ---------------- fp32 -> fp16 conversion ------------------------------------
__global__ void f32_to_f16(const float* __restrict__ src, __half2* __restrict__ dst, int n4) {
    int i = blockIdx.x * blockDim.x + threadIdx.x;
    if (i < n4) {
        float4 v = reinterpret_cast<const float4*>(src)[i];
        dst[2 * i + 0] = __floats2half2_rn(v.x, v.y);
        dst[2 * i + 1] = __floats2half2_rn(v.z, v.w);
    }
}

// pack Wq/Wk/Wv (each [L][768][768]) into [L][768][2304] fp16
__global__ void qkv_pack(const float* __restrict__ Wq, const float* __restrict__ Wk,
                         const float* __restrict__ Wv, __half2* __restrict__ dst, int n4) {
    int i = blockIdx.x * blockDim.x + threadIdx.x;
    if (i >= n4) return;
    int e = i * 4;
    int c = e % NQKV;
    int k = (e / NQKV) % DD;
    int l = e / (NQKV * DD);
    int which = c / DD;
    int n = c % DD;
    const float* W = (which == 0) ? Wq : (which == 1) ? Wk : Wv;
    float4 v = *reinterpret_cast<const float4*>(W + (size_t)l * DD * DD + (size_t)k * DD + n);
    dst[2 * i + 0] = __floats2half2_rn(v.x, v.y);
    dst[2 * i + 1] = __floats2half2_rn(v.z, v.w);
}

// ---------------- embedding + sinusoidal PE ----------------------------------
__global__ void embed_kernel(const int* __restrict__ x, const float* __restrict__ emb,
                             float* __restrict__ h, __half* __restrict__ h16) {
    int row = blockIdx.x;
    int s = row & (SS - 1);
    int tok = x[row];
    for (int c = threadIdx.x; c < DD; c += blockDim.x) {
        float ef = (float)(c & ~1) / (float)DD;
        float sc = powf(10000.0f, ef);
        float ang = (float)s / sc;
        float pe = (c & 1) ? cosf(ang) : sinf(ang);
        float v = emb[(size_t)tok * DD + c] + pe;
        h[(size_t)row * DD + c] = v;
        h16[(size_t)row * DD + c] = __float2half(v);
    }
}

// ---------------- common PTX helpers -----------------------------------------
__device__ __forceinline__ float gelu_exact(float x) {
    return 0.5f * x * (1.0f + erff(x * 0.7071067811865476f));
}

#define CPA16(dst, src) asm volatile("cp.async.cg.shared.global [%0], [%1], 16;" :: "r"(dst), "l"(src))
#define LDSM4(r0,r1,r2,r3,addr) \
    asm volatile("ldmatrix.sync.aligned.m8n8.x4.shared.b16 {%0,%1,%2,%3},[%4];" \
                 : "=r"(r0),"=r"(r1),"=r"(r2),"=r"(r3) : "r"(addr))
#define LDSM4T(r0,r1,r2,r3,addr) \
    asm volatile("ldmatrix.sync.aligned.m8n8.x4.trans.shared.b16 {%0,%1,%2,%3},[%4];" \
                 : "=r"(r0),"=r"(r1),"=r"(r2),"=r"(r3) : "r"(addr))

__device__ __forceinline__ void mma16816(float c[4], const unsigned a[4], const unsigned b[2]) {
    asm volatile("mma.sync.aligned.m16n8k16.row.col.f32.f16.f16.f32 "
                 "{%0,%1,%2,%3},{%4,%5,%6,%7},{%8,%9},{%0,%1,%2,%3};"
                 : "+f"(c[0]), "+f"(c[1]), "+f"(c[2]), "+f"(c[3])
                 : "r"(a[0]), "r"(a[1]), "r"(a[2]), "r"(a[3]), "r"(b[0]), "r"(b[1]));
}

__device__ __forceinline__ unsigned cvta_s(const void* p) {
    return (unsigned)__cvta_generic_to_shared(p);
}
__device__ __forceinline__ unsigned packh2(float x, float y) {
    __half2 h = __floats2half2_rn(x, y);
    return *reinterpret_cast<unsigned*>(&h);
}

// ---------------- fp16 tensor-core GEMM: 4-stage cp.async pipeline -----------
#define ASTR 40
#define BSTR 136
#define BBUF_H (32*BSTR)
#define NST 4
#define SMEM_GEMM_BYTES(BM) ((NST*(BM)*ASTR + NST*BBUF_H) * 2)

template<int BM, typename OutT>
__device__ __forceinline__ void gemm_body(
    const __half* __restrict__ A, const __half* __restrict__ B,
    const float* __restrict__ bias, OutT* __restrict__ C,
    int N, int K, int epi, int bx, int by, __half* sm)
{
    constexpr int MT = BM / 32;
    constexpr int ABUF_H = BM * ASTR;

    __half* As = sm;                    // [NST][BM][ASTR]
    __half* Bs = sm + NST * ABUF_H;     // [NST][32][BSTR]

    int tid = threadIdx.x;
    int lane = tid & 31;
    int warp = tid >> 5;
    int wm = warp >> 2;
    int wn = warp & 3;
    int g  = lane >> 2;
    int tg = lane & 3;

    const __half* Ab = A + (size_t)by * BM * K;
    const __half* Bb = B + (size_t)bx * 128;

    float c[MT][4][4];
    #pragma unroll
    for (int i = 0; i < MT; i++)
        #pragma unroll
        for (int j = 0; j < 4; j++)
            #pragma unroll
            for (int r = 0; r < 4; r++) c[i][j][r] = 0.f;

    const int T = K >> 5;

    auto load_tile = [&](int kt, int buf) {
        __half* Ad = As + buf * ABUF_H;
        __half* Bd = Bs + buf * BBUF_H;
        #pragma unroll
        for (int i = 0; i < BM / 64; i++) {
            int s = tid + i * 256;
            int r  = s >> 2;
            int k8 = (s & 3) * 8;
            unsigned dst = cvta_s(Ad + r * ASTR + k8);
            CPA16(dst, Ab + (size_t)r * K + kt + k8);
        }
        #pragma unroll
        for (int i = 0; i < 2; i++) {
            int s = tid + i * 256;
            int r  = s >> 4;
            int n8 = (s & 15) * 8;
            unsigned dst = cvta_s(Bd + r * BSTR + n8);
            CPA16(dst, Bb + (size_t)(kt + r) * N + n8);
        }
    };

    // prologue: stages 0..NST-2 (T >= 24 always, so no bounds checks needed)
    #pragma unroll
    for (int s = 0; s < NST - 1; s++) {
        load_tile(s * 32, s);
        asm volatile("cp.async.commit_group;");
    }

    unsigned aBase = cvta_s(As + (wm * (BM / 2) + (lane & 15)) * ASTR + (lane >> 4) * 8);
    unsigned bBase = cvta_s(Bs + (lane & 15) * BSTR + wn * 32 + (lane >> 4) * 8);

    for (int t = 0; t < T; t++) {
        asm volatile("cp.async.wait_group %0;" :: "n"(NST - 2));
        __syncthreads();

        // prefetch stage t+NST-1 into buffer (t-1)%NST (safe: consumed at iter t-1)
        int lt = t + NST - 1;
        if (lt < T) load_tile(lt * 32, lt & (NST - 1));
        asm volatile("cp.async.commit_group;");

        int st = t & (NST - 1);
        unsigned aB = aBase + st * (ABUF_H * 2);
        unsigned bB = bBase + st * (BBUF_H * 2);

        #pragma unroll
        for (int kb = 0; kb < 2; kb++) {
            unsigned a[MT][4], b[4][2];
            #pragma unroll
            for (int mt = 0; mt < MT; mt++) {
                LDSM4(a[mt][0], a[mt][1], a[mt][2], a[mt][3],
                      aB + (mt * 16 * ASTR + kb * 16) * 2);
            }
            #pragma unroll
            for (int nb = 0; nb < 2; nb++) {
                unsigned t0, t1, t2, t3;
                LDSM4T(t0, t1, t2, t3, bB + (kb * 16 * BSTR + nb * 16) * 2);
                b[2 * nb][0] = t0; b[2 * nb][1] = t1;
                b[2 * nb + 1][0] = t2; b[2 * nb + 1][1] = t3;
            }
            #pragma unroll
            for (int mt = 0; mt < MT; mt++)
                #pragma unroll
                for (int j = 0; j < 4; j++)
                    mma16816(c[mt][j], a[mt], b[j]);
        }
    }

    int colg = bx * 128 + wn * 32;
    int rowg = by * BM + wm * (BM / 2);
    #pragma unroll
    for (int mt = 0; mt < MT; mt++) {
        #pragma unroll
        for (int half = 0; half < 2; half++) {
            int row = rowg + mt * 16 + g + half * 8;
            #pragma unroll
            for (int j = 0; j < 4; j++) {
                int col = colg + j * 8 + tg * 2;
                float v0 = c[mt][j][half * 2 + 0];
                float v1 = c[mt][j][half * 2 + 1];
                if (epi >= 1) { v0 += bias[col]; v1 += bias[col + 1]; }
                if (epi == 2) { v0 = gelu_exact(v0); v1 = gelu_exact(v1); }
                if constexpr (sizeof(OutT) == 4) {
                    float2 w; w.x = v0; w.y = v1;
                    *reinterpret_cast<float2*>((float*)C + (size_t)row * N + col) = w;
                } else {
                    *reinterpret_cast<__half2*>((__half*)C + (size_t)row * N + col) =
                        __floats2half2_rn(v0, v1);
                }
            }
        }
    }
}

template<int BM, typename OutT>
__global__ __launch_bounds__(256, 2)
void gemm_f16(const __half* __restrict__ A, const __half* __restrict__ B,
              const float* __restrict__ bias, OutT* __restrict__ C,
              int N, int K, int epi)
{
    extern __shared__ __half smh[];
    gemm_body<BM, OutT>(A, B, bias, C, N, K, epi, blockIdx.x, blockIdx.y, smh);
}

// ---------------- fp16 tensor-core causal attention --------------------------
#define QSTR 72
#define KVBUF (64*QSTR)
#define ATTN_SMEM_BYTES (5 * KVBUF * 2)

__global__ __launch_bounds__(128, 4)
void attn_f16(const __half* __restrict__ qkv, __half* __restrict__ o) {
    extern __shared__ __half smh[];
    __half* Qs = smh;
    __half* Ks = smh + KVBUF;
    __half* Vs = smh + 3 * KVBUF;

    int qt = blockIdx.x;
    int bh = blockIdx.y;
    int b = bh / HH, hh = bh % HH;
    const __half* qb = qkv + (size_t)b * SS * NQKV + hh * DKK;
    const __half* kb = qb + DD;
    const __half* vb = qb + 2 * DD;

    int tid = threadIdx.x;
    int lane = tid & 31;
    int warp = tid >> 5;
    int g  = lane >> 2;
    int tg = lane & 3;

    #pragma unroll
    for (int i = 0; i < 4; i++) {
        int s = tid + i * 128;
        int r = s >> 3;
        int c8 = (s & 7) * 8;
        CPA16(cvta_s(Qs + r * QSTR + c8), qb + (size_t)(qt * 64 + r) * NQKV + c8);
    }
    auto load_kv = [&](int kt, int buf) {
        __half* Kd = Ks + buf * KVBUF;
        __half* Vd = Vs + buf * KVBUF;
        #pragma unroll
        for (int i = 0; i < 4; i++) {
            int s = tid + i * 128;
            int r = s >> 3;
            int c8 = (s & 7) * 8;
            CPA16(cvta_s(Kd + r * QSTR + c8), kb + (size_t)(kt * 64 + r) * NQKV + c8);
            CPA16(cvta_s(Vd + r * QSTR + c8), vb + (size_t)(kt * 64 + r) * NQKV + c8);
        }
    };
    load_kv(0, 0);
    asm volatile("cp.async.commit_group;");

    float oacc[8][4];
    #pragma unroll
    for (int i = 0; i < 8; i++)
        #pragma unroll
        for (int j = 0; j < 4; j++) oacc[i][j] = 0.f;
    float den0 = 0.f, den1 = 0.f;

    unsigned qAddr = cvta_s(Qs + (warp * 16 + (lane & 15)) * QSTR + (lane >> 4) * 8);
    int qg0 = qt * 64 + warp * 16 + g;

    for (int kt = 0; kt <= qt; kt++) {
        asm volatile("cp.async.wait_group 0;");
        __syncthreads();
        if (kt < qt) {
            load_kv(kt + 1, (kt + 1) & 1);
            asm volatile("cp.async.commit_group;");
        }
        const __half* Kb_ = Ks + (kt & 1) * KVBUF;
        const __half* Vb_ = Vs + (kt & 1) * KVBUF;

        float s[8][4];
        #pragma unroll
        for (int i = 0; i < 8; i++)
            #pragma unroll
            for (int j = 0; j < 4; j++) s[i][j] = 0.f;

        #pragma unroll
        for (int kbk = 0; kbk < 4; kbk++) {
            unsigned a[4];
            LDSM4(a[0], a[1], a[2], a[3], qAddr + kbk * 16 * 2);
            #pragma unroll
            for (int nb2 = 0; nb2 < 4; nb2++) {
                unsigned r0, r1, r2, r3;
                LDSM4(r0, r1, r2, r3,
                      cvta_s(Kb_ + (nb2 * 16 + (lane & 15)) * QSTR + kbk * 16 + (lane >> 4) * 8));
                unsigned b0[2] = { r0, r2 };
                unsigned b1[2] = { r1, r3 };
                mma16816(s[2 * nb2],     a, b0);
                mma16816(s[2 * nb2 + 1], a, b1);
            }
        }

        bool diag = (kt == qt);
        #pragma unroll
        for (int nb = 0; nb < 8; nb++) {
            int kg = kt * 64 + nb * 8 + 2 * tg;
            float e0 = (!diag || kg     < qg0)     ? expf(s[nb][0] * 0.125f) : 0.f;
            float e1 = (!diag || kg + 1 < qg0)     ? expf(s[nb][1] * 0.125f) : 0.f;
            float e2 = (!diag || kg     < qg0 + 8) ? expf(s[nb][2] * 0.125f) : 0.f;
            float e3 = (!diag || kg + 1 < qg0 + 8) ? expf(s[nb][3] * 0.125f) : 0.f;
            s[nb][0] = e0; s[nb][1] = e1; s[nb][2] = e2; s[nb][3] = e3;
            den0 += e0 + e1;
            den1 += e2 + e3;
        }

        #pragma unroll
        for (int kbk = 0; kbk < 4; kbk++) {
            unsigned a[4];
            a[0] = packh2(s[2 * kbk][0],     s[2 * kbk][1]);
            a[1] = packh2(s[2 * kbk][2],     s[2 * kbk][3]);
            a[2] = packh2(s[2 * kbk + 1][0], s[2 * kbk + 1][1]);
            a[3] = packh2(s[2 * kbk + 1][2], s[2 * kbk + 1][3]);
            #pragma unroll
            for (int nb2 = 0; nb2 < 4; nb2++) {
                unsigned t0, t1, t2, t3;
                LDSM4T(t0, t1, t2, t3,
                       cvta_s(Vb_ + (kbk * 16 + (lane & 15)) * QSTR + nb2 * 16 + (lane >> 4) * 8));
                unsigned b0[2] = { t0, t1 };
                unsigned b1[2] = { t2, t3 };
                mma16816(oacc[2 * nb2],     a, b0);
                mma16816(oacc[2 * nb2 + 1], a, b1);
            }
        }
    }

    den0 += __shfl_xor_sync(0xffffffffu, den0, 1);
    den0 += __shfl_xor_sync(0xffffffffu, den0, 2);
    den1 += __shfl_xor_sync(0xffffffffu, den1, 1);
    den1 += __shfl_xor_sync(0xffffffffu, den1, 2);
    float inv0 = 1.0f / (den0 + 1e-9f);
    float inv1 = 1.0f / (den1 + 1e-9f);

    int row0 = b * SS + qg0;
    #pragma unroll
    for (int nb = 0; nb < 8; nb++) {
        int col = hh * DKK + nb * 8 + 2 * tg;
        *reinterpret_cast<__half2*>(o + (size_t)row0 * DD + col) =
            __floats2half2_rn(oacc[nb][0] * inv0, oacc[nb][1] * inv0);
        *reinterpret_cast<__half2*>(o + (size_t)(row0 + 8) * DD + col) =
            __floats2half2_rn(oacc[nb][2] * inv1, oacc[nb][3] * inv1);
    }
}

// ---------------- fused residual-add + LayerNorm (writes fp32 + fp16) --------
__device__ __forceinline__ float block_reduce_sum(float v, float* sh) {
    int tid = threadIdx.x;
    #pragma unroll
    for (int o = 16; o; o >>= 1) v += __shfl_xor_sync(0xffffffffu, v, o);
    if ((tid & 31) == 0) sh[tid >> 5] = v;
    __syncthreads();
    float r = 0.f;
    if (tid < 8) r = sh[tid];
    if (tid < 32) {
        #pragma unroll
        for (int o = 4; o; o >>= 1) r += __shfl_xor_sync(0xffffffffu, r, o);
    }
    if (tid == 0) sh[0] = r;
    __syncthreads();
    float out = sh[0];
    __syncthreads();
    return out;
}

__global__ void ln_kernel(float* __restrict__ h, const float* __restrict__ delta,
                          const float* __restrict__ gs, const float* __restrict__ gb,
                          __half* __restrict__ h16) {
    __shared__ float sh[8];
    int row = blockIdx.x, tid = threadIdx.x;
    size_t base = (size_t)row * DD;
    float v[3];
    float sum = 0.f;
    #pragma unroll
    for (int t = 0; t < 3; t++) {
        int c = tid + t * 256;
        v[t] = h[base + c] + delta[base + c];
        sum += v[t];
    }
    float mean = block_reduce_sum(sum, sh) * (1.0f / 768.0f);
    float sq = 0.f;
    #pragma unroll
    for (int t = 0; t < 3; t++) { float d = v[t] - mean; sq += d * d; }
    float var = block_reduce_sum(sq, sh) * (1.0f / 768.0f);
    float inv = rsqrtf(var + 1e-5f);
    #pragma unroll
    for (int t = 0; t < 3; t++) {
        int c = tid + t * 256;
        float r = (v[t] - mean) * inv * gs[c] + gb[c];
        h[base + c] = r;
        h16[base + c] = __float2half(r);
    }
}

// ---------------- launcher ---------------------------------------------------
extern "C" void kernel_launch(void* const* d_in, const int* in_sizes, int n_in,
                              void* d_out, int out_size) {
    const int*   x     = (const int*)  d_in[0];
    const float* emb   = (const float*)d_in[1];
    const float* Wq    = (const float*)d_in[2];
    const float* Wk    = (const float*)d_in[3];
    const float* Wv    = (const float*)d_in[4];
    const float* Wo    = (const float*)d_in[5];
    const float* ln1_s = (const float*)d_in[6];
    const float* ln1_b = (const float*)d_in[7];
    const float* W1    = (const float*)d_in[8];
    const float* b1    = (const float*)d_in[9];
    const float* W2    = (const float*)d_in[10];
    const float* b2    = (const float*)d_in[11];
    const float* ln2_s = (const float*)d_in[12];
    const float* ln2_b = (const float*)d_in[13];
    const float* lm_W  = (const float*)d_in[14];
    const float* lm_b  = (const float*)d_in[15];
    float* out = (float*)d_out;

    float *h_, *tmp_;
    __half *h16_, *qkv16_, *av16_, *ff16_, *wqkv16_, *wo16_, *w116_, *w216_, *lm16_;
    cudaGetSymbolAddress((void**)&h_,     g_h);
    cudaGetSymbolAddress((void**)&tmp_,   g_tmp);
    cudaGetSymbolAddress((void**)&h16_,   g_h16);
    cudaGetSymbolAddress((void**)&qkv16_, g_qkv16);
    cudaGetSymbolAddress((void**)&av16_,  g_av16);
    cudaGetSymbolAddress((void**)&ff16_,  g_ff16);
    cudaGetSymbolAddress((void**)&wqkv16_, g_wqkv16);
    cudaGetSymbolAddress((void**)&wo16_,   g_wo16);
    cudaGetSymbolAddress((void**)&w116_,   g_w116);
    cudaGetSymbolAddress((void**)&w216_,   g_w216);
    cudaGetSymbolAddress((void**)&lm16_,   g_lm16);

    const int SM128 = SMEM_GEMM_BYTES(128);
    const int SM64  = SMEM_GEMM_BYTES(64);
    cudaFuncSetAttribute(attn_f16, cudaFuncAttributeMaxDynamicSharedMemorySize, ATTN_SMEM_BYTES);
    cudaFuncSetAttribute((const void*)gemm_f16<128, float>,  cudaFuncAttributeMaxDynamicSharedMemorySize, SM128);
    cudaFuncSetAttribute((const void*)gemm_f16<128, __half>, cudaFuncAttributeMaxDynamicSharedMemorySize, SM128);
    cudaFuncSetAttribute((const void*)gemm_f16<64, float>,   cudaFuncAttributeMaxDynamicSharedMemorySize, SM64);

    // ---- weight conversion (every launch; deterministic) ----
    {
        int n4;
        n4 = LL * DD * NQKV / 4;
        qkv_pack<<<(n4 + 255) / 256, 256>>>(Wq, Wk, Wv, (__half2*)wqkv16_, n4);
        n4 = LL * DD * DD / 4;
        f32_to_f16<<<(n4 + 255) / 256, 256>>>(Wo, (__half2*)wo16_, n4);
        n4 = LL * DD * DFFF / 4;
        f32_to_f16<<<(n4 + 255) / 256, 256>>>(W1, (__half2*)w116_, n4);
        f32_to_f16<<<(n4 + 255) / 256, 256>>>(W2, (__half2*)w216_, n4);
        n4 = DD * VV / 4;
        f32_to_f16<<<(n4 + 255) / 256, 256>>>(lm_W, (__half2*)lm16_, n4);
    }

    embed_kernel<<<MM, 256>>>(x, emb, h_, h16_);

    dim3 gQKV(NQKV / 128, MM / 128);    // (18,16)
    dim3 gN768(DD / 128, MM / 64);      // (6,32)  BM=64
    dim3 gFF1(DFFF / 128, MM / 128);    // (24,16)
    dim3 gLM(VV / 128, MM / 128);       // (250,16)
    dim3 gAttn(SS / 64, BB * HH);       // (16,24)

    for (int l = 0; l < LL; l++) {
        const __half* wqkv_l = wqkv16_ + (size_t)l * DD * NQKV;
        const __half* wo_l   = wo16_   + (size_t)l * DD * DD;
        const __half* w1_l   = w116_   + (size_t)l * DD * DFFF;
        const __half* w2_l   = w216_   + (size_t)l * DFFF * DD;

        gemm_f16<128, __half><<<gQKV, 256, SM128>>>(h16_, wqkv_l, nullptr, qkv16_, NQKV, DD, 0);

        attn_f16<<<gAttn, 128, ATTN_SMEM_BYTES>>>(qkv16_, av16_);

        gemm_f16<64, float><<<gN768, 256, SM64>>>(av16_, wo_l, nullptr, tmp_, DD, DD, 0);
        ln_kernel<<<MM, 256>>>(h_, tmp_, ln1_s + (size_t)l * DD, ln1_b + (size_t)l * DD, h16_);

        gemm_f16<128, __half><<<gFF1, 256, SM128>>>(h16_, w1_l, b1 + (size_t)l * DFFF, ff16_, DFFF, DD, 2);
        gemm_f16<64, float><<<gN768, 256, SM64>>>(ff16_, w2_l, b2 + (size_t)l * DD, tmp_, DD, DFFF, 1);
        ln_kernel<<<MM, 256>>>(h_, tmp_, ln2_s + (size_t)l * DD, ln2_b + (size_t)l * DD, h16_);
    }

    gemm_f16<128, float><<<gLM, 256, SM128>>>(h16_, lm16_, lm_b, out, VV, DD, 1);
}